// round 1
// baseline (speedup 1.0000x reference)
#include <cuda_runtime.h>

// ---------------- problem constants (fixed by dataset) ----------------
#define N_NODES 20000
#define E_MAIN  100000
#define E_BND   20000
#define E_TOT   (E_MAIN + E_BND)
#define E_PAD   100096            // E_MAIN rounded up to 128 (row-block aligned)
#define EB_PAD  20096             // E_BND  rounded up to 128
#define ROWS_TOT (E_PAD + EB_PAD) // 120192, multiple of 128
#define WIDTH   32
#define KW      64
#define DEPTH   4

// ---------------- device scratch (no allocations allowed) ----------------
__device__ float g_h0[N_NODES * WIDTH];
__device__ float g_h [N_NODES * WIDTH];
__device__ float g_agg[N_NODES * WIDTH];
__device__ float g_cnt1[N_NODES];
__device__ float g_cnt2[N_NODES];
__device__ float g_inv1[N_NODES];
__device__ float g_inv2[N_NODES];
__device__ float g_khid[(size_t)ROWS_TOT * KW];        // 30.8 MB
__device__ float g_W[(size_t)ROWS_TOT * 1024];          // 492 MB: per-edge 32x32 weights
__device__ float g_rootsum[WIDTH * WIDTH];
__device__ float g_biassum[WIDTH];

// ---------------- tiny kernels ----------------
__global__ void fc1_kernel(const float* __restrict__ x,
                           const float* __restrict__ w,
                           const float* __restrict__ b) {
    int i = blockIdx.x * blockDim.x + threadIdx.x;
    if (i >= N_NODES * WIDTH) return;
    int n = i >> 5, c = i & 31;
    float v = fmaf(x[n], w[c], b[c]);
    g_h0[i] = v;
    g_h[i]  = v;
}

__global__ void zero_cnt_kernel() {
    int i = blockIdx.x * blockDim.x + threadIdx.x;
    if (i < N_NODES) { g_cnt1[i] = 0.f; g_cnt2[i] = 0.f; }
}

__global__ void zero_agg_kernel() {
    int i = blockIdx.x * blockDim.x + threadIdx.x;
    if (i < N_NODES * WIDTH) g_agg[i] = 0.f;
}

__global__ void count_kernel(const int* __restrict__ ei,
                             const int* __restrict__ eib) {
    int e = blockIdx.x * blockDim.x + threadIdx.x;
    if (e < E_MAIN) {
        atomicAdd(&g_cnt1[ei[E_MAIN + e]], 1.0f);
    } else if (e < E_TOT) {
        int eb = e - E_MAIN;
        atomicAdd(&g_cnt2[eib[E_BND + eb]], 1.0f);
    }
}

__global__ void inv_kernel() {
    int n = blockIdx.x * blockDim.x + threadIdx.x;
    if (n >= N_NODES) return;
    g_inv1[n] = 1.0f / fmaxf(g_cnt1[n], 1.0f);
    g_inv2[n] = 1.0f / fmaxf(g_cnt2[n], 1.0f);
}

__global__ void rootsum_kernel(const float* __restrict__ r1, const float* __restrict__ b1,
                               const float* __restrict__ r2, const float* __restrict__ b2) {
    int t = threadIdx.x;
    if (t < WIDTH * WIDTH) g_rootsum[t] = r1[t] + r2[t];
    if (t < WIDTH)         g_biassum[t] = b1[t] + b2[t];
}

// ---------------- kernel MLP: edge_attr(6) -> relu 64 -> relu 64 ----------------
// one warp per edge; lane j computes hidden units j and j+32
__global__ void __launch_bounds__(256) kermlp_kernel(
    const float* __restrict__ ea1, const float* __restrict__ ea2,
    const float* __restrict__ k1w1, const float* __restrict__ k1b1,
    const float* __restrict__ k1w2, const float* __restrict__ k1b2,
    const float* __restrict__ k2w1, const float* __restrict__ k2b1,
    const float* __restrict__ k2w2, const float* __restrict__ k2b2)
{
    __shared__ float sw1[2][6 * 64];
    __shared__ float sb1[2][64];
    __shared__ float sw2[2][64 * 64];
    __shared__ float sb2[2][64];
    int t = threadIdx.x;
    for (int i = t; i < 6 * 64; i += 256) { sw1[0][i] = k1w1[i]; sw1[1][i] = k2w1[i]; }
    for (int i = t; i < 64; i += 256) {
        sb1[0][i] = k1b1[i]; sb1[1][i] = k2b1[i];
        sb2[0][i] = k1b2[i]; sb2[1][i] = k2b2[i];
    }
    for (int i = t; i < 64 * 64; i += 256) { sw2[0][i] = k1w2[i]; sw2[1][i] = k2w2[i]; }
    __syncthreads();

    int warp = t >> 5, lane = t & 31;
    int e = blockIdx.x * 8 + warp;
    if (e >= E_TOT) return;

    int set; size_t row; const float* ea;
    if (e < E_MAIN) { set = 0; row = (size_t)e; ea = ea1 + (size_t)e * 6; }
    else { set = 1; int eb = e - E_MAIN; row = (size_t)E_PAD + eb; ea = ea2 + (size_t)eb * 6; }

    float eav = (lane < 6) ? ea[lane] : 0.f;

    float h1a = sb1[set][lane], h1b = sb1[set][lane + 32];
    #pragma unroll
    for (int i = 0; i < 6; i++) {
        float v = __shfl_sync(0xffffffffu, eav, i);
        h1a = fmaf(v, sw1[set][i * 64 + lane], h1a);
        h1b = fmaf(v, sw1[set][i * 64 + lane + 32], h1b);
    }
    h1a = fmaxf(h1a, 0.f); h1b = fmaxf(h1b, 0.f);

    float h2a = sb2[set][lane], h2b = sb2[set][lane + 32];
    #pragma unroll
    for (int i = 0; i < 64; i++) {
        float v = __shfl_sync(0xffffffffu, (i < 32) ? h1a : h1b, i & 31);
        h2a = fmaf(v, sw2[set][i * 64 + lane], h2a);
        h2b = fmaf(v, sw2[set][i * 64 + lane + 32], h2b);
    }
    h2a = fmaxf(h2a, 0.f); h2b = fmaxf(h2b, 0.f);

    g_khid[row * 64 + lane]      = h2a;
    g_khid[row * 64 + lane + 32] = h2b;
}

// ---------------- W = khid @ w3 + b3 : [ROWS_TOT,64] @ [64,1024] ----------------
// 128x128 block tile, K split into 2 tiles of 32, 8x8 per-thread microtile.
__global__ void __launch_bounds__(256) w3gemm_kernel(
    const float* __restrict__ w3a, const float* __restrict__ b3a,
    const float* __restrict__ w3b, const float* __restrict__ b3b)
{
    __shared__ float As[32 * 132];   // [k][row], padded stride 132 (16B aligned)
    __shared__ float Bs[32 * 128];   // [k][col]

    int rb = blockIdx.x;             // 0..938
    int cb = blockIdx.y;             // 0..7
    size_t r0 = (size_t)rb * 128;
    const float* w3 = (r0 >= (size_t)E_PAD) ? w3b : w3a;
    const float* b3 = (r0 >= (size_t)E_PAD) ? b3b : b3a;

    int t  = threadIdx.x;
    int tx = t & 15;                 // col group: cols tx*8 .. +7
    int ty = t >> 4;                 // row group: rows ty*8 .. +7

    float acc[8][8];
    #pragma unroll
    for (int i = 0; i < 8; i++)
        #pragma unroll
        for (int j = 0; j < 8; j++) acc[i][j] = 0.f;

    const float4* A4 = (const float4*)(g_khid + r0 * 64);

    #pragma unroll
    for (int kt = 0; kt < 2; kt++) {
        // --- load A tile (coalesced float4, transpose into As[k][row]) ---
        #pragma unroll
        for (int i = 0; i < 4; i++) {
            int idx = t + 256 * i;            // 0..1023
            int r  = idx >> 3;                // 0..127
            int k4 = idx & 7;                 // 0..7
            float4 v = A4[(size_t)r * 16 + kt * 8 + k4];
            As[(k4 * 4 + 0) * 132 + r] = v.x;
            As[(k4 * 4 + 1) * 132 + r] = v.y;
            As[(k4 * 4 + 2) * 132 + r] = v.z;
            As[(k4 * 4 + 3) * 132 + r] = v.w;
        }
        // --- load B tile (coalesced float4) ---
        #pragma unroll
        for (int i = 0; i < 4; i++) {
            int idx = t + 256 * i;            // 0..1023
            int kr = idx >> 5;                // 0..31
            int c4 = idx & 31;                // 0..31
            float4 v = *(const float4*)(w3 + (size_t)(kt * 32 + kr) * 1024 + cb * 128 + c4 * 4);
            *(float4*)(Bs + kr * 128 + c4 * 4) = v;
        }
        __syncthreads();

        #pragma unroll
        for (int k = 0; k < 32; k++) {
            float4 a0 = *(const float4*)(As + k * 132 + ty * 8);
            float4 a1 = *(const float4*)(As + k * 132 + ty * 8 + 4);
            float4 b0 = *(const float4*)(Bs + k * 128 + tx * 8);
            float4 b1 = *(const float4*)(Bs + k * 128 + tx * 8 + 4);
            float a[8] = {a0.x, a0.y, a0.z, a0.w, a1.x, a1.y, a1.z, a1.w};
            float b[8] = {b0.x, b0.y, b0.z, b0.w, b1.x, b1.y, b1.z, b1.w};
            #pragma unroll
            for (int i = 0; i < 8; i++)
                #pragma unroll
                for (int j = 0; j < 8; j++)
                    acc[i][j] = fmaf(a[i], b[j], acc[i][j]);
        }
        __syncthreads();
    }

    // --- epilogue: add b3, store ---
    int colbase = cb * 128 + tx * 8;
    float bb[8];
    #pragma unroll
    for (int j = 0; j < 8; j++) bb[j] = b3[colbase + j];
    #pragma unroll
    for (int i = 0; i < 8; i++) {
        size_t row = r0 + ty * 8 + i;
        float* out = g_W + row * 1024 + colbase;
        float4 o0 = {acc[i][0] + bb[0], acc[i][1] + bb[1], acc[i][2] + bb[2], acc[i][3] + bb[3]};
        float4 o1 = {acc[i][4] + bb[4], acc[i][5] + bb[5], acc[i][6] + bb[6], acc[i][7] + bb[7]};
        *(float4*)(out)     = o0;
        *(float4*)(out + 4) = o1;
    }
}

// ---------------- per-edge message + scaled scatter-add ----------------
// one warp per edge; lane o owns output channel o.
__global__ void __launch_bounds__(256) edge_msg_kernel(const int* __restrict__ ei,
                                                       const int* __restrict__ eib)
{
    int w = (blockIdx.x * blockDim.x + threadIdx.x) >> 5;
    int lane = threadIdx.x & 31;
    if (w >= E_TOT) return;

    int src, dst; size_t wrow; float scale;
    if (w < E_MAIN) {
        src = ei[w]; dst = ei[E_MAIN + w];
        wrow = (size_t)w;
        scale = g_inv1[dst];
    } else {
        int eb = w - E_MAIN;
        src = eib[eb]; dst = eib[E_BND + eb];
        wrow = (size_t)E_PAD + eb;
        scale = g_inv2[dst];
    }

    float hv = g_h[src * WIDTH + lane];
    const float* __restrict__ Wp = g_W + wrow * 1024;
    float msg = 0.f;
    #pragma unroll
    for (int i = 0; i < 32; i++) {
        float hi = __shfl_sync(0xffffffffu, hv, i);
        msg = fmaf(hi, Wp[i * 32 + lane], msg);
    }
    atomicAdd(&g_agg[dst * WIDTH + lane], msg * scale);
}

// ---------------- node update: h = relu(agg + h@(root1+root2) + b1+b2) + h0 ----------------
__global__ void __launch_bounds__(256) node_update_kernel() {
    int n = (blockIdx.x * blockDim.x + threadIdx.x) >> 5;
    int lane = threadIdx.x & 31;
    if (n >= N_NODES) return;

    float hv  = g_h[n * WIDTH + lane];
    float acc = g_agg[n * WIDTH + lane] + g_biassum[lane];
    #pragma unroll
    for (int i = 0; i < 32; i++) {
        float hi = __shfl_sync(0xffffffffu, hv, i);
        acc = fmaf(hi, g_rootsum[i * 32 + lane], acc);
    }
    g_h[n * WIDTH + lane] = fmaxf(acc, 0.f) + g_h0[n * WIDTH + lane];
}

// ---------------- output: out = h @ fc2_w + fc2_b ----------------
__global__ void __launch_bounds__(256) fc2_kernel(const float* __restrict__ w,
                                                  const float* __restrict__ b,
                                                  float* __restrict__ out) {
    int n = (blockIdx.x * blockDim.x + threadIdx.x) >> 5;
    int lane = threadIdx.x & 31;
    if (n >= N_NODES) return;
    float v = g_h[n * WIDTH + lane] * w[lane];
    #pragma unroll
    for (int off = 16; off > 0; off >>= 1)
        v += __shfl_xor_sync(0xffffffffu, v, off);
    if (lane == 0) out[n] = v + b[0];
}

// ---------------- host orchestration (graph-capturable: launches only) ----------------
extern "C" void kernel_launch(void* const* d_in, const int* in_sizes, int n_in,
                              void* d_out, int out_size) {
    const float* x    = (const float*)d_in[0];
    const int*   ei   = (const int*)  d_in[1];
    const float* ea   = (const float*)d_in[2];
    const int*   eib  = (const int*)  d_in[3];
    const float* eab  = (const float*)d_in[4];
    const float* fc1w = (const float*)d_in[5];
    const float* fc1b = (const float*)d_in[6];
    const float* fc2w = (const float*)d_in[7];
    const float* fc2b = (const float*)d_in[8];
    const float* k1w1 = (const float*)d_in[9];
    const float* k1b1 = (const float*)d_in[10];
    const float* k1w2 = (const float*)d_in[11];
    const float* k1b2 = (const float*)d_in[12];
    const float* k1w3 = (const float*)d_in[13];
    const float* k1b3 = (const float*)d_in[14];
    const float* root1= (const float*)d_in[15];
    const float* bias1= (const float*)d_in[16];
    const float* k2w1 = (const float*)d_in[17];
    const float* k2b1 = (const float*)d_in[18];
    const float* k2w2 = (const float*)d_in[19];
    const float* k2b2 = (const float*)d_in[20];
    const float* k2w3 = (const float*)d_in[21];
    const float* k2b3 = (const float*)d_in[22];
    const float* root2= (const float*)d_in[23];
    const float* bias2= (const float*)d_in[24];
    float* out = (float*)d_out;

    // h0 = x@fc1 ; h = h0
    fc1_kernel<<<(N_NODES * WIDTH + 255) / 256, 256>>>(x, fc1w, fc1b);

    // per-node mean divisors (loop-invariant)
    zero_cnt_kernel<<<(N_NODES + 255) / 256, 256>>>();
    count_kernel<<<(E_TOT + 255) / 256, 256>>>(ei, eib);
    inv_kernel<<<(N_NODES + 255) / 256, 256>>>();

    // root1+root2, bias1+bias2 (loop-invariant)
    rootsum_kernel<<<1, 1024>>>(root1, bias1, root2, bias2);

    // kernel MLP hidden (loop-invariant)
    kermlp_kernel<<<(E_TOT + 7) / 8, 256>>>(ea, eab,
                                            k1w1, k1b1, k1w2, k1b2,
                                            k2w1, k2b1, k2w2, k2b2);

    // per-edge 32x32 weight matrices (loop-invariant): W = khid @ w3 + b3
    dim3 ggrid(ROWS_TOT / 128, 1024 / 128);
    w3gemm_kernel<<<ggrid, 256>>>(k1w3, k1b3, k2w3, k2b3);

    // DEPTH message-passing steps
    for (int d = 0; d < DEPTH; d++) {
        zero_agg_kernel<<<(N_NODES * WIDTH + 255) / 256, 256>>>();
        edge_msg_kernel<<<(E_TOT * 32 + 255) / 256, 256>>>(ei, eib);
        node_update_kernel<<<(N_NODES * 32 + 255) / 256, 256>>>();
    }

    // out = h @ fc2 + b
    fc2_kernel<<<(N_NODES * 32 + 255) / 256, 256>>>(fc2w, fc2b, out);
}

// round 3
// speedup vs baseline: 1.1652x; 1.1652x over previous
#include <cuda_runtime.h>
#include <cuda_fp16.h>

// ---------------- problem constants (fixed by dataset) ----------------
#define N_NODES 20000
#define E_MAIN  100000
#define E_BND   20000
#define E_TOT   (E_MAIN + E_BND)
#define E_PAD   100096            // E_MAIN rounded up to 128 (row-block aligned)
#define EB_PAD  20096             // E_BND  rounded up to 128
#define ROWS_TOT (E_PAD + EB_PAD) // 120192, multiple of 128
#define WIDTH   32
#define KW      64
#define DEPTH   4

// ---------------- device scratch (no allocations allowed) ----------------
__device__ float g_h0[N_NODES * WIDTH];
__device__ float g_h [N_NODES * WIDTH];
__device__ float g_agg[N_NODES * WIDTH];
__device__ float g_cnt1[N_NODES];
__device__ float g_cnt2[N_NODES];
__device__ float g_inv1[N_NODES];
__device__ float g_inv2[N_NODES];
__device__ float g_khid[(size_t)ROWS_TOT * KW];        // 30.8 MB
__device__ __half g_Wh[(size_t)ROWS_TOT * 1024];       // 246 MB: per-edge 32x32 weights, fp16
// layout within a row's 1024 halves: element (i,o) at (i>>2)*128 + o*4 + (i&3)
__device__ float g_rootsum[WIDTH * WIDTH];
__device__ float g_biassum[WIDTH];

// ---------------- tiny kernels ----------------
__global__ void fc1_kernel(const float* __restrict__ x,
                           const float* __restrict__ w,
                           const float* __restrict__ b) {
    int i = blockIdx.x * blockDim.x + threadIdx.x;
    if (i >= N_NODES * WIDTH) return;
    int n = i >> 5, c = i & 31;
    float v = fmaf(x[n], w[c], b[c]);
    g_h0[i] = v;
    g_h[i]  = v;
}

__global__ void zero_cnt_kernel() {
    int i = blockIdx.x * blockDim.x + threadIdx.x;
    if (i < N_NODES) { g_cnt1[i] = 0.f; g_cnt2[i] = 0.f; }
}

__global__ void zero_agg_kernel() {
    int i = blockIdx.x * blockDim.x + threadIdx.x;
    if (i < N_NODES * WIDTH) g_agg[i] = 0.f;
}

__global__ void count_kernel(const int* __restrict__ ei,
                             const int* __restrict__ eib) {
    int e = blockIdx.x * blockDim.x + threadIdx.x;
    if (e < E_MAIN) {
        atomicAdd(&g_cnt1[ei[E_MAIN + e]], 1.0f);
    } else if (e < E_TOT) {
        int eb = e - E_MAIN;
        atomicAdd(&g_cnt2[eib[E_BND + eb]], 1.0f);
    }
}

__global__ void inv_kernel() {
    int n = blockIdx.x * blockDim.x + threadIdx.x;
    if (n >= N_NODES) return;
    g_inv1[n] = 1.0f / fmaxf(g_cnt1[n], 1.0f);
    g_inv2[n] = 1.0f / fmaxf(g_cnt2[n], 1.0f);
}

__global__ void rootsum_kernel(const float* __restrict__ r1, const float* __restrict__ b1,
                               const float* __restrict__ r2, const float* __restrict__ b2) {
    int t = threadIdx.x;
    if (t < WIDTH * WIDTH) g_rootsum[t] = r1[t] + r2[t];
    if (t < WIDTH)         g_biassum[t] = b1[t] + b2[t];
}

// ---------------- kernel MLP: edge_attr(6) -> relu 64 -> relu 64 ----------------
__global__ void __launch_bounds__(256) kermlp_kernel(
    const float* __restrict__ ea1, const float* __restrict__ ea2,
    const float* __restrict__ k1w1, const float* __restrict__ k1b1,
    const float* __restrict__ k1w2, const float* __restrict__ k1b2,
    const float* __restrict__ k2w1, const float* __restrict__ k2b1,
    const float* __restrict__ k2w2, const float* __restrict__ k2b2)
{
    __shared__ float sw1[2][6 * 64];
    __shared__ float sb1[2][64];
    __shared__ float sw2[2][64 * 64];
    __shared__ float sb2[2][64];
    int t = threadIdx.x;
    for (int i = t; i < 6 * 64; i += 256) { sw1[0][i] = k1w1[i]; sw1[1][i] = k2w1[i]; }
    for (int i = t; i < 64; i += 256) {
        sb1[0][i] = k1b1[i]; sb1[1][i] = k2b1[i];
        sb2[0][i] = k1b2[i]; sb2[1][i] = k2b2[i];
    }
    for (int i = t; i < 64 * 64; i += 256) { sw2[0][i] = k1w2[i]; sw2[1][i] = k2w2[i]; }
    __syncthreads();

    int warp = t >> 5, lane = t & 31;
    int e = blockIdx.x * 8 + warp;
    if (e >= E_TOT) return;

    int set; size_t row; const float* ea;
    if (e < E_MAIN) { set = 0; row = (size_t)e; ea = ea1 + (size_t)e * 6; }
    else { set = 1; int eb = e - E_MAIN; row = (size_t)E_PAD + eb; ea = ea2 + (size_t)eb * 6; }

    float eav = (lane < 6) ? ea[lane] : 0.f;

    float h1a = sb1[set][lane], h1b = sb1[set][lane + 32];
    #pragma unroll
    for (int i = 0; i < 6; i++) {
        float v = __shfl_sync(0xffffffffu, eav, i);
        h1a = fmaf(v, sw1[set][i * 64 + lane], h1a);
        h1b = fmaf(v, sw1[set][i * 64 + lane + 32], h1b);
    }
    h1a = fmaxf(h1a, 0.f); h1b = fmaxf(h1b, 0.f);

    float h2a = sb2[set][lane], h2b = sb2[set][lane + 32];
    #pragma unroll
    for (int i = 0; i < 64; i++) {
        float v = __shfl_sync(0xffffffffu, (i < 32) ? h1a : h1b, i & 31);
        h2a = fmaf(v, sw2[set][i * 64 + lane], h2a);
        h2b = fmaf(v, sw2[set][i * 64 + lane + 32], h2b);
    }
    h2a = fmaxf(h2a, 0.f); h2b = fmaxf(h2b, 0.f);

    g_khid[row * 64 + lane]      = h2a;
    g_khid[row * 64 + lane + 32] = h2b;
}

// ---------------- W = khid @ w3 + b3 : [ROWS_TOT,64] @ [64,1024] -> fp16 ----------------
__global__ void __launch_bounds__(256) w3gemm_kernel(
    const float* __restrict__ w3a, const float* __restrict__ b3a,
    const float* __restrict__ w3b, const float* __restrict__ b3b)
{
    __shared__ float As[32 * 132];   // [k][row], padded stride 132
    __shared__ float Bs[32 * 128];   // [k][col]

    int rb = blockIdx.x;
    int cb = blockIdx.y;
    size_t r0 = (size_t)rb * 128;
    const float* w3 = (r0 >= (size_t)E_PAD) ? w3b : w3a;
    const float* b3 = (r0 >= (size_t)E_PAD) ? b3b : b3a;

    int t  = threadIdx.x;
    int tx = t & 15;                 // col group: cols tx*8 .. +7
    int ty = t >> 4;                 // row group: rows ty*8 .. +7

    float acc[8][8];
    #pragma unroll
    for (int i = 0; i < 8; i++)
        #pragma unroll
        for (int j = 0; j < 8; j++) acc[i][j] = 0.f;

    const float4* A4 = (const float4*)(g_khid + r0 * 64);

    #pragma unroll
    for (int kt = 0; kt < 2; kt++) {
        #pragma unroll
        for (int i = 0; i < 4; i++) {
            int idx = t + 256 * i;
            int r  = idx >> 3;
            int k4 = idx & 7;
            float4 v = A4[(size_t)r * 16 + kt * 8 + k4];
            As[(k4 * 4 + 0) * 132 + r] = v.x;
            As[(k4 * 4 + 1) * 132 + r] = v.y;
            As[(k4 * 4 + 2) * 132 + r] = v.z;
            As[(k4 * 4 + 3) * 132 + r] = v.w;
        }
        #pragma unroll
        for (int i = 0; i < 4; i++) {
            int idx = t + 256 * i;
            int kr = idx >> 5;
            int c4 = idx & 31;
            float4 v = *(const float4*)(w3 + (size_t)(kt * 32 + kr) * 1024 + cb * 128 + c4 * 4);
            *(float4*)(Bs + kr * 128 + c4 * 4) = v;
        }
        __syncthreads();

        #pragma unroll
        for (int k = 0; k < 32; k++) {
            float4 a0 = *(const float4*)(As + k * 132 + ty * 8);
            float4 a1 = *(const float4*)(As + k * 132 + ty * 8 + 4);
            float4 b0 = *(const float4*)(Bs + k * 128 + tx * 8);
            float4 b1 = *(const float4*)(Bs + k * 128 + tx * 8 + 4);
            float a[8] = {a0.x, a0.y, a0.z, a0.w, a1.x, a1.y, a1.z, a1.w};
            float b[8] = {b0.x, b0.y, b0.z, b0.w, b1.x, b1.y, b1.z, b1.w};
            #pragma unroll
            for (int i = 0; i < 8; i++)
                #pragma unroll
                for (int j = 0; j < 8; j++)
                    acc[i][j] = fmaf(a[i], b[j], acc[i][j]);
        }
        __syncthreads();
    }

    // --- epilogue: add b3, convert fp16, store in interleaved layout ---
    // GEMM col c = cb*128 + tx*8 + j ; W-matrix coords: i = c>>5 (const per
    // thread, since tx*8 blocks never straddle a 32 boundary), o = c&31.
    int colbase = cb * 128 + tx * 8;
    int i_idx = colbase >> 5;
    int obase = colbase & 31;
    float bb[8];
    #pragma unroll
    for (int j = 0; j < 8; j++) bb[j] = b3[colbase + j];

    size_t dbase = ((size_t)(i_idx >> 2)) * 128 + (i_idx & 3);
    #pragma unroll
    for (int r = 0; r < 8; r++) {
        size_t row = r0 + ty * 8 + r;
        __half* out = g_Wh + row * 1024 + dbase;
        #pragma unroll
        for (int j = 0; j < 8; j++)
            out[(size_t)(obase + j) * 4] = __float2half_rn(acc[r][j] + bb[j]);
    }
}

// ---------------- per-edge message + scaled scatter-add (fp16 W) ----------------
// one warp per edge; lane o owns output channel o.
__global__ void __launch_bounds__(256) edge_msg_kernel(const int* __restrict__ ei,
                                                       const int* __restrict__ eib)
{
    int w = (blockIdx.x * blockDim.x + threadIdx.x) >> 5;
    int lane = threadIdx.x & 31;
    if (w >= E_TOT) return;

    int src, dst; size_t wrow; float scale;
    if (w < E_MAIN) {
        src = ei[w]; dst = ei[E_MAIN + w];
        wrow = (size_t)w;
        scale = g_inv1[dst];
    } else {
        int eb = w - E_MAIN;
        src = eib[eb]; dst = eib[E_BND + eb];
        wrow = (size_t)E_PAD + eb;
        scale = g_inv2[dst];
    }

    float hv = g_h[src * WIDTH + lane];
    const __half* __restrict__ Wp = g_Wh + wrow * 1024;
    float msg = 0.f;
    #pragma unroll
    for (int j = 0; j < 8; j++) {
        // 4 halves: W(i=4j..4j+3, o=lane), contiguous 8B per lane, 256B/warp
        uint2 v = *(const uint2*)(Wp + (size_t)j * 128 + lane * 4);
        __half2 p0 = *reinterpret_cast<const __half2*>(&v.x);
        __half2 p1 = *reinterpret_cast<const __half2*>(&v.y);
        float2 f0 = __half22float2(p0);
        float2 f1 = __half22float2(p1);
        float h0 = __shfl_sync(0xffffffffu, hv, 4 * j + 0);
        float h1 = __shfl_sync(0xffffffffu, hv, 4 * j + 1);
        float h2 = __shfl_sync(0xffffffffu, hv, 4 * j + 2);
        float h3 = __shfl_sync(0xffffffffu, hv, 4 * j + 3);
        msg = fmaf(f0.x, h0, msg);
        msg = fmaf(f0.y, h1, msg);
        msg = fmaf(f1.x, h2, msg);
        msg = fmaf(f1.y, h3, msg);
    }
    atomicAdd(&g_agg[dst * WIDTH + lane], msg * scale);
}

// ---------------- node update (consumes + re-zeroes agg; optionally fc2) ------
__global__ void __launch_bounds__(256) node_update_kernel(int last,
                                                          const float* __restrict__ fc2w,
                                                          const float* __restrict__ fc2b,
                                                          float* __restrict__ out) {
    int n = (blockIdx.x * blockDim.x + threadIdx.x) >> 5;
    int lane = threadIdx.x & 31;
    if (n >= N_NODES) return;

    float hv  = g_h[n * WIDTH + lane];
    float acc = g_agg[n * WIDTH + lane] + g_biassum[lane];
    g_agg[n * WIDTH + lane] = 0.f;   // ready for next pass
    #pragma unroll
    for (int i = 0; i < 32; i++) {
        float hi = __shfl_sync(0xffffffffu, hv, i);
        acc = fmaf(hi, g_rootsum[i * 32 + lane], acc);
    }
    float hnew = fmaxf(acc, 0.f) + g_h0[n * WIDTH + lane];
    g_h[n * WIDTH + lane] = hnew;

    if (last) {
        float v = hnew * fc2w[lane];
        #pragma unroll
        for (int off = 16; off > 0; off >>= 1)
            v += __shfl_xor_sync(0xffffffffu, v, off);
        if (lane == 0) out[n] = v + fc2b[0];
    }
}

// ---------------- host orchestration ----------------
extern "C" void kernel_launch(void* const* d_in, const int* in_sizes, int n_in,
                              void* d_out, int out_size) {
    const float* x    = (const float*)d_in[0];
    const int*   ei   = (const int*)  d_in[1];
    const float* ea   = (const float*)d_in[2];
    const int*   eib  = (const int*)  d_in[3];
    const float* eab  = (const float*)d_in[4];
    const float* fc1w = (const float*)d_in[5];
    const float* fc1b = (const float*)d_in[6];
    const float* fc2w = (const float*)d_in[7];
    const float* fc2b = (const float*)d_in[8];
    const float* k1w1 = (const float*)d_in[9];
    const float* k1b1 = (const float*)d_in[10];
    const float* k1w2 = (const float*)d_in[11];
    const float* k1b2 = (const float*)d_in[12];
    const float* k1w3 = (const float*)d_in[13];
    const float* k1b3 = (const float*)d_in[14];
    const float* root1= (const float*)d_in[15];
    const float* bias1= (const float*)d_in[16];
    const float* k2w1 = (const float*)d_in[17];
    const float* k2b1 = (const float*)d_in[18];
    const float* k2w2 = (const float*)d_in[19];
    const float* k2b2 = (const float*)d_in[20];
    const float* k2w3 = (const float*)d_in[21];
    const float* k2b3 = (const float*)d_in[22];
    const float* root2= (const float*)d_in[23];
    const float* bias2= (const float*)d_in[24];
    float* out = (float*)d_out;

    fc1_kernel<<<(N_NODES * WIDTH + 255) / 256, 256>>>(x, fc1w, fc1b);

    zero_cnt_kernel<<<(N_NODES + 255) / 256, 256>>>();
    zero_agg_kernel<<<(N_NODES * WIDTH + 255) / 256, 256>>>();
    count_kernel<<<(E_TOT + 255) / 256, 256>>>(ei, eib);
    inv_kernel<<<(N_NODES + 255) / 256, 256>>>();
    rootsum_kernel<<<1, 1024>>>(root1, bias1, root2, bias2);

    kermlp_kernel<<<(E_TOT + 7) / 8, 256>>>(ea, eab,
                                            k1w1, k1b1, k1w2, k1b2,
                                            k2w1, k2b1, k2w2, k2b2);

    dim3 ggrid(ROWS_TOT / 128, 1024 / 128);
    w3gemm_kernel<<<ggrid, 256>>>(k1w3, k1b3, k2w3, k2b3);

    for (int d = 0; d < DEPTH; d++) {
        edge_msg_kernel<<<(E_TOT * 32 + 255) / 256, 256>>>(ei, eib);
        node_update_kernel<<<(N_NODES * 32 + 255) / 256, 256>>>(
            d == DEPTH - 1 ? 1 : 0, fc2w, fc2b, out);
    }
}

// round 4
// speedup vs baseline: 1.6231x; 1.3930x over previous
#include <cuda_runtime.h>
#include <cuda_fp16.h>
#include <stdint.h>

// ---------------- problem constants (fixed by dataset) ----------------
#define N_NODES 20000
#define E_MAIN  100000
#define E_BND   20000
#define E_TOT   (E_MAIN + E_BND)
#define E_PAD   100096            // E_MAIN rounded up to 128
#define EB_PAD  20096             // E_BND  rounded up to 128
#define ROWS_TOT (E_PAD + EB_PAD) // 120192, multiple of 128
#define WIDTH   32
#define KW      64
#define DEPTH   4

// ---------------- device scratch (no allocations allowed) ----------------
__device__ float g_h0[N_NODES * WIDTH];
__device__ float g_h [N_NODES * WIDTH];
__device__ float g_agg[N_NODES * WIDTH];
__device__ float g_cnt1[N_NODES];
__device__ float g_cnt2[N_NODES];
__device__ float g_inv1[N_NODES];
__device__ float g_inv2[N_NODES];
__device__ __align__(16) __half g_khid[(size_t)ROWS_TOT * KW];   // 15.4 MB, fp16
__device__ __align__(16) __half g_w3h[2][KW * 1024];             // fp16 copy of k1_w3/k2_w3
__device__ __align__(16) __half g_Wh[(size_t)ROWS_TOT * 1024];   // 246 MB per-edge weights
// layout within a row's 1024 halves: element (i,o) at (i>>2)*128 + o*4 + (i&3)
__device__ float g_rootsum[WIDTH * WIDTH];
__device__ float g_biassum[WIDTH];

// ---------------- tiny kernels ----------------
__global__ void fc1_kernel(const float* __restrict__ x,
                           const float* __restrict__ w,
                           const float* __restrict__ b) {
    int i = blockIdx.x * blockDim.x + threadIdx.x;
    if (i >= N_NODES * WIDTH) return;
    int n = i >> 5, c = i & 31;
    float v = fmaf(x[n], w[c], b[c]);
    g_h0[i] = v;
    g_h[i]  = v;
}

__global__ void zero_cnt_kernel() {
    int i = blockIdx.x * blockDim.x + threadIdx.x;
    if (i < N_NODES) { g_cnt1[i] = 0.f; g_cnt2[i] = 0.f; }
}

__global__ void zero_agg_kernel() {
    int i = blockIdx.x * blockDim.x + threadIdx.x;
    if (i < N_NODES * WIDTH) g_agg[i] = 0.f;
}

__global__ void count_kernel(const int* __restrict__ ei,
                             const int* __restrict__ eib) {
    int e = blockIdx.x * blockDim.x + threadIdx.x;
    if (e < E_MAIN) {
        atomicAdd(&g_cnt1[ei[E_MAIN + e]], 1.0f);
    } else if (e < E_TOT) {
        int eb = e - E_MAIN;
        atomicAdd(&g_cnt2[eib[E_BND + eb]], 1.0f);
    }
}

__global__ void inv_kernel() {
    int n = blockIdx.x * blockDim.x + threadIdx.x;
    if (n >= N_NODES) return;
    g_inv1[n] = 1.0f / fmaxf(g_cnt1[n], 1.0f);
    g_inv2[n] = 1.0f / fmaxf(g_cnt2[n], 1.0f);
}

__global__ void rootsum_kernel(const float* __restrict__ r1, const float* __restrict__ b1,
                               const float* __restrict__ r2, const float* __restrict__ b2) {
    int t = threadIdx.x;
    if (t < WIDTH * WIDTH) g_rootsum[t] = r1[t] + r2[t];
    if (t < WIDTH)         g_biassum[t] = b1[t] + b2[t];
}

__global__ void convw3_kernel(const float* __restrict__ w3a,
                              const float* __restrict__ w3b) {
    int i = blockIdx.x * blockDim.x + threadIdx.x;
    if (i < KW * 1024) {
        g_w3h[0][i] = __float2half_rn(w3a[i]);
        g_w3h[1][i] = __float2half_rn(w3b[i]);
    }
}

// ---------------- kernel MLP: edge_attr(6) -> relu 64 -> relu 64 (fp16 out) ----
__global__ void __launch_bounds__(256) kermlp_kernel(
    const float* __restrict__ ea1, const float* __restrict__ ea2,
    const float* __restrict__ k1w1, const float* __restrict__ k1b1,
    const float* __restrict__ k1w2, const float* __restrict__ k1b2,
    const float* __restrict__ k2w1, const float* __restrict__ k2b1,
    const float* __restrict__ k2w2, const float* __restrict__ k2b2)
{
    __shared__ float sw1[2][6 * 64];
    __shared__ float sb1[2][64];
    __shared__ float sw2[2][64 * 64];
    __shared__ float sb2[2][64];
    int t = threadIdx.x;
    for (int i = t; i < 6 * 64; i += 256) { sw1[0][i] = k1w1[i]; sw1[1][i] = k2w1[i]; }
    for (int i = t; i < 64; i += 256) {
        sb1[0][i] = k1b1[i]; sb1[1][i] = k2b1[i];
        sb2[0][i] = k1b2[i]; sb2[1][i] = k2b2[i];
    }
    for (int i = t; i < 64 * 64; i += 256) { sw2[0][i] = k1w2[i]; sw2[1][i] = k2w2[i]; }
    __syncthreads();

    int warp = t >> 5, lane = t & 31;
    int e = blockIdx.x * 8 + warp;
    if (e >= E_TOT) return;

    int set; size_t row; const float* ea;
    if (e < E_MAIN) { set = 0; row = (size_t)e; ea = ea1 + (size_t)e * 6; }
    else { set = 1; int eb = e - E_MAIN; row = (size_t)E_PAD + eb; ea = ea2 + (size_t)eb * 6; }

    float eav = (lane < 6) ? ea[lane] : 0.f;

    float h1a = sb1[set][lane], h1b = sb1[set][lane + 32];
    #pragma unroll
    for (int i = 0; i < 6; i++) {
        float v = __shfl_sync(0xffffffffu, eav, i);
        h1a = fmaf(v, sw1[set][i * 64 + lane], h1a);
        h1b = fmaf(v, sw1[set][i * 64 + lane + 32], h1b);
    }
    h1a = fmaxf(h1a, 0.f); h1b = fmaxf(h1b, 0.f);

    float h2a = sb2[set][lane], h2b = sb2[set][lane + 32];
    #pragma unroll
    for (int i = 0; i < 64; i++) {
        float v = __shfl_sync(0xffffffffu, (i < 32) ? h1a : h1b, i & 31);
        h2a = fmaf(v, sw2[set][i * 64 + lane], h2a);
        h2b = fmaf(v, sw2[set][i * 64 + lane + 32], h2b);
    }
    h2a = fmaxf(h2a, 0.f); h2b = fmaxf(h2b, 0.f);

    g_khid[row * 64 + lane]      = __float2half_rn(h2a);
    g_khid[row * 64 + lane + 32] = __float2half_rn(h2b);
}

// ---------------- W = khid @ w3 + b3 via HMMA m16n8k16 ----------------
// block = 128 rows x 128 cols, 8 warps (2 row x 4 col), warp tile 64x32.
// K=64 fully resident in smem. Epilogue stages interleaved layout in smem
// and writes coalesced 16B stores.
__global__ void __launch_bounds__(256) w3gemm_kernel(
    const float* __restrict__ b3a, const float* __restrict__ b3b)
{
    __shared__ union {
        struct {
            __half A[128 * 72];   // [row][k], stride 72 halves
            __half B[128 * 72];   // [n][k],   stride 72 halves (transposed w3 tile)
        } in;
        __half E[128 * 136];      // epilogue staging, stride 136 halves
    } sm;
    __shared__ float sbias[128];

    int rb = blockIdx.x, cb = blockIdx.y;
    size_t r0 = (size_t)rb * 128;
    int set = (r0 >= (size_t)E_PAD) ? 1 : 0;
    const float* b3 = set ? b3b : b3a;
    int t = threadIdx.x;

    if (t < 128) sbias[t] = b3[cb * 128 + t];

    // load A tile: 128 rows x 64 halves (8-half vector loads)
    const __half* Ag = g_khid + r0 * 64;
    #pragma unroll
    for (int i = 0; i < 4; i++) {
        int idx = t + 256 * i;          // 0..1023
        int r = idx >> 3, c8 = idx & 7;
        *(uint4*)&sm.in.A[r * 72 + c8 * 8] = *(const uint4*)&Ag[r * 64 + c8 * 8];
    }
    // load B tile transposed: w3h [64 k][1024] slice -> Bs[n][k]
    const __half* Bg = g_w3h[set] + cb * 128;
    #pragma unroll
    for (int i = 0; i < 4; i++) {
        int idx = t + 256 * i;          // 0..1023
        int k = idx >> 4, n8 = idx & 15;
        uint4 v = *(const uint4*)&Bg[(size_t)k * 1024 + n8 * 8];
        const __half* hv = (const __half*)&v;
        #pragma unroll
        for (int j = 0; j < 8; j++)
            sm.in.B[(n8 * 8 + j) * 72 + k] = hv[j];
    }
    __syncthreads();

    int w = t >> 5, lane = t & 31;
    int wr = (w & 1) * 64;              // warp row base
    int wc = (w >> 1) * 32;             // warp col base
    int qrow = lane >> 2;               // 0..7
    int qk2  = (lane & 3) * 2;          // 0,2,4,6

    float acc[4][4][4];
    #pragma unroll
    for (int rf = 0; rf < 4; rf++)
        #pragma unroll
        for (int cf = 0; cf < 4; cf++)
            #pragma unroll
            for (int v = 0; v < 4; v++) acc[rf][cf][v] = 0.f;

    #pragma unroll
    for (int ks = 0; ks < 4; ks++) {
        int k0 = ks * 16;
        uint32_t a[4][4], b[4][2];
        #pragma unroll
        for (int rf = 0; rf < 4; rf++) {
            const __half* ap = &sm.in.A[(wr + rf * 16 + qrow) * 72 + k0 + qk2];
            a[rf][0] = *(const uint32_t*)ap;             // rows r,   k..k+1
            a[rf][1] = *(const uint32_t*)(ap + 8 * 72);  // rows r+8, k..k+1
            a[rf][2] = *(const uint32_t*)(ap + 8);       // rows r,   k+8..k+9
            a[rf][3] = *(const uint32_t*)(ap + 8 * 72 + 8);
        }
        #pragma unroll
        for (int cf = 0; cf < 4; cf++) {
            const __half* bp = &sm.in.B[(wc + cf * 8 + qrow) * 72 + k0 + qk2];
            b[cf][0] = *(const uint32_t*)bp;             // k..k+1
            b[cf][1] = *(const uint32_t*)(bp + 8);       // k+8..k+9
        }
        #pragma unroll
        for (int rf = 0; rf < 4; rf++)
            #pragma unroll
            for (int cf = 0; cf < 4; cf++)
                asm volatile(
                    "mma.sync.aligned.m16n8k16.row.col.f32.f16.f16.f32 "
                    "{%0,%1,%2,%3}, {%4,%5,%6,%7}, {%8,%9}, {%0,%1,%2,%3};"
                    : "+f"(acc[rf][cf][0]), "+f"(acc[rf][cf][1]),
                      "+f"(acc[rf][cf][2]), "+f"(acc[rf][cf][3])
                    : "r"(a[rf][0]), "r"(a[rf][1]), "r"(a[rf][2]), "r"(a[rf][3]),
                      "r"(b[cf][0]), "r"(b[cf][1]));
    }
    __syncthreads();   // A/B tiles dead; reuse smem for epilogue

    // epilogue: bias add, fp16 convert, write interleaved layout into E.
    // GEMM col cbl -> dest (cbl & 31)*4 + (cbl >> 5)   (block-local, cb*4 i-base)
    #pragma unroll
    for (int rf = 0; rf < 4; rf++) {
        int row = wr + rf * 16 + qrow;
        #pragma unroll
        for (int cf = 0; cf < 4; cf++) {
            int cbl = wc + cf * 8 + (lane & 3) * 2;     // even, pair cbl,cbl+1
            int dest = (cbl & 31) * 4 + (cbl >> 5);     // cbl+1 -> dest+4
            sm.E[row * 136 + dest]           = __float2half_rn(acc[rf][cf][0] + sbias[cbl]);
            sm.E[row * 136 + dest + 4]       = __float2half_rn(acc[rf][cf][1] + sbias[cbl + 1]);
            sm.E[(row + 8) * 136 + dest]     = __float2half_rn(acc[rf][cf][2] + sbias[cbl]);
            sm.E[(row + 8) * 136 + dest + 4] = __float2half_rn(acc[rf][cf][3] + sbias[cbl + 1]);
        }
    }
    __syncthreads();

    // coalesced copy out: 128 rows x 128 halves
    #pragma unroll
    for (int i = 0; i < 8; i++) {
        int idx = t + 256 * i;          // 0..2047
        int r = idx >> 4, c8 = idx & 15;
        *(uint4*)&g_Wh[(r0 + r) * 1024 + cb * 128 + c8 * 8] =
            *(const uint4*)&sm.E[r * 136 + c8 * 8];
    }
}

// ---------------- per-edge message + scaled scatter-add (fp16 W) ----------------
__global__ void __launch_bounds__(256) edge_msg_kernel(const int* __restrict__ ei,
                                                       const int* __restrict__ eib)
{
    int w = (blockIdx.x * blockDim.x + threadIdx.x) >> 5;
    int lane = threadIdx.x & 31;
    if (w >= E_TOT) return;

    int src, dst; size_t wrow; float scale;
    if (w < E_MAIN) {
        src = ei[w]; dst = ei[E_MAIN + w];
        wrow = (size_t)w;
        scale = g_inv1[dst];
    } else {
        int eb = w - E_MAIN;
        src = eib[eb]; dst = eib[E_BND + eb];
        wrow = (size_t)E_PAD + eb;
        scale = g_inv2[dst];
    }

    float hv = g_h[src * WIDTH + lane];
    const __half* __restrict__ Wp = g_Wh + wrow * 1024;
    float msg = 0.f;
    #pragma unroll
    for (int j = 0; j < 8; j++) {
        uint2 v = *(const uint2*)(Wp + (size_t)j * 128 + lane * 4);
        __half2 p0 = *reinterpret_cast<const __half2*>(&v.x);
        __half2 p1 = *reinterpret_cast<const __half2*>(&v.y);
        float2 f0 = __half22float2(p0);
        float2 f1 = __half22float2(p1);
        float h0 = __shfl_sync(0xffffffffu, hv, 4 * j + 0);
        float h1 = __shfl_sync(0xffffffffu, hv, 4 * j + 1);
        float h2 = __shfl_sync(0xffffffffu, hv, 4 * j + 2);
        float h3 = __shfl_sync(0xffffffffu, hv, 4 * j + 3);
        msg = fmaf(f0.x, h0, msg);
        msg = fmaf(f0.y, h1, msg);
        msg = fmaf(f1.x, h2, msg);
        msg = fmaf(f1.y, h3, msg);
    }
    atomicAdd(&g_agg[dst * WIDTH + lane], msg * scale);
}

// ---------------- node update (consumes + re-zeroes agg; optionally fc2) ------
__global__ void __launch_bounds__(256) node_update_kernel(int last,
                                                          const float* __restrict__ fc2w,
                                                          const float* __restrict__ fc2b,
                                                          float* __restrict__ out) {
    int n = (blockIdx.x * blockDim.x + threadIdx.x) >> 5;
    int lane = threadIdx.x & 31;
    if (n >= N_NODES) return;

    float hv  = g_h[n * WIDTH + lane];
    float acc = g_agg[n * WIDTH + lane] + g_biassum[lane];
    g_agg[n * WIDTH + lane] = 0.f;   // ready for next pass
    #pragma unroll
    for (int i = 0; i < 32; i++) {
        float hi = __shfl_sync(0xffffffffu, hv, i);
        acc = fmaf(hi, g_rootsum[i * 32 + lane], acc);
    }
    float hnew = fmaxf(acc, 0.f) + g_h0[n * WIDTH + lane];
    g_h[n * WIDTH + lane] = hnew;

    if (last) {
        float v = hnew * fc2w[lane];
        #pragma unroll
        for (int off = 16; off > 0; off >>= 1)
            v += __shfl_xor_sync(0xffffffffu, v, off);
        if (lane == 0) out[n] = v + fc2b[0];
    }
}

// ---------------- host orchestration ----------------
extern "C" void kernel_launch(void* const* d_in, const int* in_sizes, int n_in,
                              void* d_out, int out_size) {
    const float* x    = (const float*)d_in[0];
    const int*   ei   = (const int*)  d_in[1];
    const float* ea   = (const float*)d_in[2];
    const int*   eib  = (const int*)  d_in[3];
    const float* eab  = (const float*)d_in[4];
    const float* fc1w = (const float*)d_in[5];
    const float* fc1b = (const float*)d_in[6];
    const float* fc2w = (const float*)d_in[7];
    const float* fc2b = (const float*)d_in[8];
    const float* k1w1 = (const float*)d_in[9];
    const float* k1b1 = (const float*)d_in[10];
    const float* k1w2 = (const float*)d_in[11];
    const float* k1b2 = (const float*)d_in[12];
    const float* k1w3 = (const float*)d_in[13];
    const float* k1b3 = (const float*)d_in[14];
    const float* root1= (const float*)d_in[15];
    const float* bias1= (const float*)d_in[16];
    const float* k2w1 = (const float*)d_in[17];
    const float* k2b1 = (const float*)d_in[18];
    const float* k2w2 = (const float*)d_in[19];
    const float* k2b2 = (const float*)d_in[20];
    const float* k2w3 = (const float*)d_in[21];
    const float* k2b3 = (const float*)d_in[22];
    const float* root2= (const float*)d_in[23];
    const float* bias2= (const float*)d_in[24];
    float* out = (float*)d_out;

    fc1_kernel<<<(N_NODES * WIDTH + 255) / 256, 256>>>(x, fc1w, fc1b);

    zero_cnt_kernel<<<(N_NODES + 255) / 256, 256>>>();
    zero_agg_kernel<<<(N_NODES * WIDTH + 255) / 256, 256>>>();
    count_kernel<<<(E_TOT + 255) / 256, 256>>>(ei, eib);
    inv_kernel<<<(N_NODES + 255) / 256, 256>>>();
    rootsum_kernel<<<1, 1024>>>(root1, bias1, root2, bias2);
    convw3_kernel<<<(KW * 1024 + 255) / 256, 256>>>(k1w3, k2w3);

    kermlp_kernel<<<(E_TOT + 7) / 8, 256>>>(ea, eab,
                                            k1w1, k1b1, k1w2, k1b2,
                                            k2w1, k2b1, k2w2, k2b2);

    dim3 ggrid(ROWS_TOT / 128, 1024 / 128);
    w3gemm_kernel<<<ggrid, 256>>>(k1b3, k2b3);

    for (int d = 0; d < DEPTH; d++) {
        edge_msg_kernel<<<(E_TOT * 32 + 255) / 256, 256>>>(ei, eib);
        node_update_kernel<<<(N_NODES * 32 + 255) / 256, 256>>>(
            d == DEPTH - 1 ? 1 : 0, fc2w, fc2b, out);
    }
}

// round 5
// speedup vs baseline: 1.9317x; 1.1902x over previous
#include <cuda_runtime.h>
#include <cuda_fp16.h>
#include <stdint.h>

// ---------------- problem constants (fixed by dataset) ----------------
#define N_NODES 20000
#define E_MAIN  100000
#define E_BND   20000
#define E_TOT   (E_MAIN + E_BND)
#define E_PAD   100096            // E_MAIN rounded up to 128
#define EB_PAD  20096             // E_BND  rounded up to 128
#define ROWS_TOT (E_PAD + EB_PAD) // 120192, multiple of 128
#define WIDTH   32
#define KW      64
#define DEPTH   4

// ---------------- device scratch (no allocations allowed) ----------------
__device__ float g_h0[N_NODES * WIDTH];
__device__ float g_h [N_NODES * WIDTH];
__device__ float g_agg[N_NODES * WIDTH];
__device__ float g_cnt1[N_NODES];
__device__ float g_cnt2[N_NODES];
__device__ float g_inv1[N_NODES];
__device__ float g_inv2[N_NODES];
__device__ __align__(16) __half g_khid[(size_t)ROWS_TOT * KW];   // 15.4 MB, fp16
__device__ __align__(16) __half g_w3h[2][KW * 1024];             // fp16 copy of k1_w3/k2_w3
__device__ __align__(16) __half g_Wh[(size_t)ROWS_TOT * 1024];   // 246 MB per-edge weights
// layout within a row's 1024 halves: element (i,o) at (i>>2)*128 + o*4 + (i&3)
__device__ float g_rootsum[WIDTH * WIDTH];
__device__ float g_biassum[WIDTH];

// ---------------- fused setup A: fc1 + zero agg + zero cnt ----------------
__global__ void setupA_kernel(const float* __restrict__ x,
                              const float* __restrict__ w,
                              const float* __restrict__ b) {
    int i = blockIdx.x * blockDim.x + threadIdx.x;
    if (i < N_NODES * WIDTH) {
        int n = i >> 5, c = i & 31;
        float v = fmaf(x[n], w[c], b[c]);
        g_h0[i] = v;
        g_h[i]  = v;
        g_agg[i] = 0.f;
    }
    if (i < N_NODES) { g_cnt1[i] = 0.f; g_cnt2[i] = 0.f; }
}

__global__ void count_kernel(const int* __restrict__ ei,
                             const int* __restrict__ eib) {
    int e = blockIdx.x * blockDim.x + threadIdx.x;
    if (e < E_MAIN) {
        atomicAdd(&g_cnt1[ei[E_MAIN + e]], 1.0f);
    } else if (e < E_TOT) {
        int eb = e - E_MAIN;
        atomicAdd(&g_cnt2[eib[E_BND + eb]], 1.0f);
    }
}

// ---------------- fused setup B: inv + rootsum + convw3 ----------------
__global__ void setupB_kernel(const float* __restrict__ r1, const float* __restrict__ b1,
                              const float* __restrict__ r2, const float* __restrict__ b2,
                              const float* __restrict__ w3a, const float* __restrict__ w3b) {
    int i = blockIdx.x * blockDim.x + threadIdx.x;
    if (i < KW * 1024) {
        g_w3h[0][i] = __float2half_rn(w3a[i]);
        g_w3h[1][i] = __float2half_rn(w3b[i]);
    }
    if (i < N_NODES) {
        g_inv1[i] = 1.0f / fmaxf(g_cnt1[i], 1.0f);
        g_inv2[i] = 1.0f / fmaxf(g_cnt2[i], 1.0f);
    }
    if (i < WIDTH * WIDTH) g_rootsum[i] = r1[i] + r2[i];
    if (i < WIDTH)         g_biassum[i] = b1[i] + b2[i];
}

// ---------------- kernel MLP: edge_attr(6) -> relu 64 -> relu 64 (fp16 out) ----
__global__ void __launch_bounds__(256) kermlp_kernel(
    const float* __restrict__ ea1, const float* __restrict__ ea2,
    const float* __restrict__ k1w1, const float* __restrict__ k1b1,
    const float* __restrict__ k1w2, const float* __restrict__ k1b2,
    const float* __restrict__ k2w1, const float* __restrict__ k2b1,
    const float* __restrict__ k2w2, const float* __restrict__ k2b2)
{
    __shared__ float sw1[2][6 * 64];
    __shared__ float sb1[2][64];
    __shared__ float sw2[2][64 * 64];
    __shared__ float sb2[2][64];
    int t = threadIdx.x;
    for (int i = t; i < 6 * 64; i += 256) { sw1[0][i] = k1w1[i]; sw1[1][i] = k2w1[i]; }
    for (int i = t; i < 64; i += 256) {
        sb1[0][i] = k1b1[i]; sb1[1][i] = k2b1[i];
        sb2[0][i] = k1b2[i]; sb2[1][i] = k2b2[i];
    }
    for (int i = t; i < 64 * 64; i += 256) { sw2[0][i] = k1w2[i]; sw2[1][i] = k2w2[i]; }
    __syncthreads();

    int warp = t >> 5, lane = t & 31;
    int e = blockIdx.x * 8 + warp;
    if (e >= E_TOT) return;

    int set; size_t row; const float* ea;
    if (e < E_MAIN) { set = 0; row = (size_t)e; ea = ea1 + (size_t)e * 6; }
    else { set = 1; int eb = e - E_MAIN; row = (size_t)E_PAD + eb; ea = ea2 + (size_t)eb * 6; }

    float eav = (lane < 6) ? ea[lane] : 0.f;

    float h1a = sb1[set][lane], h1b = sb1[set][lane + 32];
    #pragma unroll
    for (int i = 0; i < 6; i++) {
        float v = __shfl_sync(0xffffffffu, eav, i);
        h1a = fmaf(v, sw1[set][i * 64 + lane], h1a);
        h1b = fmaf(v, sw1[set][i * 64 + lane + 32], h1b);
    }
    h1a = fmaxf(h1a, 0.f); h1b = fmaxf(h1b, 0.f);

    float h2a = sb2[set][lane], h2b = sb2[set][lane + 32];
    #pragma unroll
    for (int i = 0; i < 64; i++) {
        float v = __shfl_sync(0xffffffffu, (i < 32) ? h1a : h1b, i & 31);
        h2a = fmaf(v, sw2[set][i * 64 + lane], h2a);
        h2b = fmaf(v, sw2[set][i * 64 + lane + 32], h2b);
    }
    h2a = fmaxf(h2a, 0.f); h2b = fmaxf(h2b, 0.f);

    g_khid[row * 64 + lane]      = __float2half_rn(h2a);
    g_khid[row * 64 + lane + 32] = __float2half_rn(h2b);
}

// ---------------- W = khid @ w3 + b3 via HMMA m16n8k16 ----------------
// block = 128 rows x 128 cols, 8 warps (2 row x 4 col), warp tile 64x32.
// B tile stored [n][k] with XOR swizzle on k (bank-conflict-free).
__global__ void __launch_bounds__(256) w3gemm_kernel(
    const float* __restrict__ b3a, const float* __restrict__ b3b)
{
    __shared__ union {
        struct {
            __half A[128 * 72];   // [row][k], stride 72 halves
            __half B[128 * 72];   // [n][k^swz], stride 72 halves
        } in;
        __half E[128 * 136];      // epilogue staging, stride 136 halves
    } sm;
    __shared__ float sbias[128];

    int rb = blockIdx.x, cb = blockIdx.y;
    size_t r0 = (size_t)rb * 128;
    int set = (r0 >= (size_t)E_PAD) ? 1 : 0;
    const float* b3 = set ? b3b : b3a;
    int t = threadIdx.x;

    if (t < 128) sbias[t] = b3[cb * 128 + t];

    // load A tile: 128 rows x 64 halves (8-half vector loads)
    const __half* Ag = g_khid + r0 * 64;
    #pragma unroll
    for (int i = 0; i < 4; i++) {
        int idx = t + 256 * i;          // 0..1023
        int r = idx >> 3, c8 = idx & 7;
        *(uint4*)&sm.in.A[r * 72 + c8 * 8] = *(const uint4*)&Ag[r * 64 + c8 * 8];
    }
    // load B tile transposed with XOR swizzle: (n,k) -> B[n*72 + (k ^ ((n8&7)*8))]
    const __half* Bg = g_w3h[set] + cb * 128;
    #pragma unroll
    for (int i = 0; i < 4; i++) {
        int idx = t + 256 * i;          // 0..1023
        int k = idx >> 4, n8 = idx & 15;
        uint4 v = *(const uint4*)&Bg[(size_t)k * 1024 + n8 * 8];
        const __half* hv = (const __half*)&v;
        int ksw = k ^ ((n8 & 7) * 8);
        #pragma unroll
        for (int j = 0; j < 8; j++)
            sm.in.B[(n8 * 8 + j) * 72 + ksw] = hv[j];
    }
    __syncthreads();

    int w = t >> 5, lane = t & 31;
    int wr = (w & 1) * 64;              // warp row base
    int wc = (w >> 1) * 32;             // warp col base
    int qrow = lane >> 2;               // 0..7
    int qk2  = (lane & 3) * 2;          // 0,2,4,6

    float acc[4][4][4];
    #pragma unroll
    for (int rf = 0; rf < 4; rf++)
        #pragma unroll
        for (int cf = 0; cf < 4; cf++)
            #pragma unroll
            for (int v = 0; v < 4; v++) acc[rf][cf][v] = 0.f;

    #pragma unroll
    for (int ks = 0; ks < 4; ks++) {
        int k0 = ks * 16;
        uint32_t a[4][4], b[4][2];
        #pragma unroll
        for (int rf = 0; rf < 4; rf++) {
            const __half* ap = &sm.in.A[(wr + rf * 16 + qrow) * 72 + k0 + qk2];
            a[rf][0] = *(const uint32_t*)ap;             // rows r,   k..k+1
            a[rf][1] = *(const uint32_t*)(ap + 8 * 72);  // rows r+8, k..k+1
            a[rf][2] = *(const uint32_t*)(ap + 8);       // rows r,   k+8..k+9
            a[rf][3] = *(const uint32_t*)(ap + 8 * 72 + 8);
        }
        #pragma unroll
        for (int cf = 0; cf < 4; cf++) {
            int n = wc + cf * 8 + qrow;
            int xorv = ((n >> 3) & 7) * 8;               // const per fragment
            // even k ^ xorv keeps k,k+1 adjacent (xor touches bits>=3)
            b[cf][0] = *(const uint32_t*)&sm.in.B[n * 72 + ((k0 + qk2) ^ xorv)];
            b[cf][1] = *(const uint32_t*)&sm.in.B[n * 72 + ((k0 + qk2 + 8) ^ xorv)];
        }
        #pragma unroll
        for (int rf = 0; rf < 4; rf++)
            #pragma unroll
            for (int cf = 0; cf < 4; cf++)
                asm volatile(
                    "mma.sync.aligned.m16n8k16.row.col.f32.f16.f16.f32 "
                    "{%0,%1,%2,%3}, {%4,%5,%6,%7}, {%8,%9}, {%0,%1,%2,%3};"
                    : "+f"(acc[rf][cf][0]), "+f"(acc[rf][cf][1]),
                      "+f"(acc[rf][cf][2]), "+f"(acc[rf][cf][3])
                    : "r"(a[rf][0]), "r"(a[rf][1]), "r"(a[rf][2]), "r"(a[rf][3]),
                      "r"(b[cf][0]), "r"(b[cf][1]));
    }
    __syncthreads();   // A/B tiles dead; reuse smem for epilogue

    // epilogue: bias add, fp16 convert, interleaved layout into E.
    #pragma unroll
    for (int rf = 0; rf < 4; rf++) {
        int row = wr + rf * 16 + qrow;
        #pragma unroll
        for (int cf = 0; cf < 4; cf++) {
            int cbl = wc + cf * 8 + (lane & 3) * 2;     // even, pair cbl,cbl+1
            int dest = (cbl & 31) * 4 + (cbl >> 5);     // cbl+1 -> dest+4
            sm.E[row * 136 + dest]           = __float2half_rn(acc[rf][cf][0] + sbias[cbl]);
            sm.E[row * 136 + dest + 4]       = __float2half_rn(acc[rf][cf][1] + sbias[cbl + 1]);
            sm.E[(row + 8) * 136 + dest]     = __float2half_rn(acc[rf][cf][2] + sbias[cbl]);
            sm.E[(row + 8) * 136 + dest + 4] = __float2half_rn(acc[rf][cf][3] + sbias[cbl + 1]);
        }
    }
    __syncthreads();

    // coalesced copy out: 128 rows x 128 halves
    #pragma unroll
    for (int i = 0; i < 8; i++) {
        int idx = t + 256 * i;          // 0..2047
        int r = idx >> 4, c8 = idx & 15;
        *(uint4*)&g_Wh[(r0 + r) * 1024 + cb * 128 + c8 * 8] =
            *(const uint4*)&sm.E[r * 136 + c8 * 8];
    }
}

// ---------------- per-edge message: 2 edges per warp ----------------
// pairs (2w, 2w+1) never straddle the main/boundary split (E_MAIN even).
__global__ void __launch_bounds__(256) edge_msg_kernel(const int* __restrict__ ei,
                                                       const int* __restrict__ eib)
{
    int w = (blockIdx.x * blockDim.x + threadIdx.x) >> 5;
    int lane = threadIdx.x & 31;
    int e0 = 2 * w;
    if (e0 >= E_TOT) return;

    int src0, dst0, src1, dst1; size_t wr0, wr1; float sc0, sc1;
    if (e0 < E_MAIN) {
        src0 = ei[e0];     dst0 = ei[E_MAIN + e0];
        src1 = ei[e0 + 1]; dst1 = ei[E_MAIN + e0 + 1];
        wr0 = (size_t)e0; wr1 = (size_t)e0 + 1;
        sc0 = g_inv1[dst0]; sc1 = g_inv1[dst1];
    } else {
        int eb = e0 - E_MAIN;
        src0 = eib[eb];     dst0 = eib[E_BND + eb];
        src1 = eib[eb + 1]; dst1 = eib[E_BND + eb + 1];
        wr0 = (size_t)E_PAD + eb; wr1 = (size_t)E_PAD + eb + 1;
        sc0 = g_inv2[dst0]; sc1 = g_inv2[dst1];
    }

    float hv0 = g_h[src0 * WIDTH + lane];
    float hv1 = g_h[src1 * WIDTH + lane];
    const __half* __restrict__ W0 = g_Wh + wr0 * 1024;
    const __half* __restrict__ W1 = g_Wh + wr1 * 1024;
    float m0 = 0.f, m1 = 0.f;
    #pragma unroll
    for (int j = 0; j < 8; j++) {
        uint2 v0 = *(const uint2*)(W0 + (size_t)j * 128 + lane * 4);
        uint2 v1 = *(const uint2*)(W1 + (size_t)j * 128 + lane * 4);
        float2 a0 = __half22float2(*reinterpret_cast<const __half2*>(&v0.x));
        float2 a1 = __half22float2(*reinterpret_cast<const __half2*>(&v0.y));
        float2 b0 = __half22float2(*reinterpret_cast<const __half2*>(&v1.x));
        float2 b1 = __half22float2(*reinterpret_cast<const __half2*>(&v1.y));
        float h00 = __shfl_sync(0xffffffffu, hv0, 4 * j + 0);
        float h01 = __shfl_sync(0xffffffffu, hv0, 4 * j + 1);
        float h02 = __shfl_sync(0xffffffffu, hv0, 4 * j + 2);
        float h03 = __shfl_sync(0xffffffffu, hv0, 4 * j + 3);
        float h10 = __shfl_sync(0xffffffffu, hv1, 4 * j + 0);
        float h11 = __shfl_sync(0xffffffffu, hv1, 4 * j + 1);
        float h12 = __shfl_sync(0xffffffffu, hv1, 4 * j + 2);
        float h13 = __shfl_sync(0xffffffffu, hv1, 4 * j + 3);
        m0 = fmaf(a0.x, h00, m0); m0 = fmaf(a0.y, h01, m0);
        m0 = fmaf(a1.x, h02, m0); m0 = fmaf(a1.y, h03, m0);
        m1 = fmaf(b0.x, h10, m1); m1 = fmaf(b0.y, h11, m1);
        m1 = fmaf(b1.x, h12, m1); m1 = fmaf(b1.y, h13, m1);
    }
    atomicAdd(&g_agg[dst0 * WIDTH + lane], m0 * sc0);
    atomicAdd(&g_agg[dst1 * WIDTH + lane], m1 * sc1);
}

// ---------------- node update (consumes + re-zeroes agg; optionally fc2) ------
__global__ void __launch_bounds__(256) node_update_kernel(int last,
                                                          const float* __restrict__ fc2w,
                                                          const float* __restrict__ fc2b,
                                                          float* __restrict__ out) {
    int n = (blockIdx.x * blockDim.x + threadIdx.x) >> 5;
    int lane = threadIdx.x & 31;
    if (n >= N_NODES) return;

    float hv  = g_h[n * WIDTH + lane];
    float acc = g_agg[n * WIDTH + lane] + g_biassum[lane];
    g_agg[n * WIDTH + lane] = 0.f;   // ready for next pass
    #pragma unroll
    for (int i = 0; i < 32; i++) {
        float hi = __shfl_sync(0xffffffffu, hv, i);
        acc = fmaf(hi, g_rootsum[i * 32 + lane], acc);
    }
    float hnew = fmaxf(acc, 0.f) + g_h0[n * WIDTH + lane];
    g_h[n * WIDTH + lane] = hnew;

    if (last) {
        float v = hnew * fc2w[lane];
        #pragma unroll
        for (int off = 16; off > 0; off >>= 1)
            v += __shfl_xor_sync(0xffffffffu, v, off);
        if (lane == 0) out[n] = v + fc2b[0];
    }
}

// ---------------- host orchestration ----------------
extern "C" void kernel_launch(void* const* d_in, const int* in_sizes, int n_in,
                              void* d_out, int out_size) {
    const float* x    = (const float*)d_in[0];
    const int*   ei   = (const int*)  d_in[1];
    const float* ea   = (const float*)d_in[2];
    const int*   eib  = (const int*)  d_in[3];
    const float* eab  = (const float*)d_in[4];
    const float* fc1w = (const float*)d_in[5];
    const float* fc1b = (const float*)d_in[6];
    const float* fc2w = (const float*)d_in[7];
    const float* fc2b = (const float*)d_in[8];
    const float* k1w1 = (const float*)d_in[9];
    const float* k1b1 = (const float*)d_in[10];
    const float* k1w2 = (const float*)d_in[11];
    const float* k1b2 = (const float*)d_in[12];
    const float* k1w3 = (const float*)d_in[13];
    const float* k1b3 = (const float*)d_in[14];
    const float* root1= (const float*)d_in[15];
    const float* bias1= (const float*)d_in[16];
    const float* k2w1 = (const float*)d_in[17];
    const float* k2b1 = (const float*)d_in[18];
    const float* k2w2 = (const float*)d_in[19];
    const float* k2b2 = (const float*)d_in[20];
    const float* k2w3 = (const float*)d_in[21];
    const float* k2b3 = (const float*)d_in[22];
    const float* root2= (const float*)d_in[23];
    const float* bias2= (const float*)d_in[24];
    float* out = (float*)d_out;

    // launch order chosen so ncu (-s 5 -c 1) captures edge_msg_kernel (6th)
    setupA_kernel<<<(N_NODES * WIDTH + 255) / 256, 256>>>(x, fc1w, fc1b);      // 1
    count_kernel<<<(E_TOT + 255) / 256, 256>>>(ei, eib);                       // 2
    setupB_kernel<<<(KW * 1024 + 255) / 256, 256>>>(root1, bias1, root2, bias2,
                                                    k1w3, k2w3);               // 3
    kermlp_kernel<<<(E_TOT + 7) / 8, 256>>>(ea, eab,
                                            k1w1, k1b1, k1w2, k1b2,
                                            k2w1, k2b1, k2w2, k2b2);           // 4
    dim3 ggrid(ROWS_TOT / 128, 1024 / 128);
    w3gemm_kernel<<<ggrid, 256>>>(k1b3, k2b3);                                 // 5

    for (int d = 0; d < DEPTH; d++) {
        edge_msg_kernel<<<(E_TOT / 2 * 32 + 255) / 256, 256>>>(ei, eib);       // 6 on d=0
        node_update_kernel<<<(N_NODES * 32 + 255) / 256, 256>>>(
            d == DEPTH - 1 ? 1 : 0, fc2w, fc2b, out);
    }
}

// round 9
// speedup vs baseline: 2.5787x; 1.3349x over previous
#include <cuda_runtime.h>
#include <cuda_fp16.h>
#include <stdint.h>

// ---------------- problem constants (fixed by dataset) ----------------
#define N_NODES 20000
#define E_MAIN  100000
#define E_BND   20000
#define E_TOT   (E_MAIN + E_BND)
#define E_PAD   100096            // E_MAIN rounded up to 128
#define EB_PAD  20096             // E_BND  rounded up to 128
#define ROWS_TOT (E_PAD + EB_PAD) // 120192, multiple of 128
#define WIDTH   32
#define KW      64
#define DEPTH   4

// ---------------- device scratch (no allocations allowed) ----------------
__device__ float g_h0[N_NODES * WIDTH];
__device__ float g_h [N_NODES * WIDTH];
__device__ float g_agg[N_NODES * WIDTH];
__device__ float g_cnt1[N_NODES];
__device__ float g_cnt2[N_NODES];
__device__ float g_inv1[N_NODES];
__device__ float g_inv2[N_NODES];
__device__ __align__(16) __half g_khid[(size_t)ROWS_TOT * KW];   // 15.4 MB, fp16
__device__ __align__(16) __half g_w2h[2][KW * KW];               // fp16 k1_w2/k2_w2
__device__ __align__(16) __half g_w3h[2][KW * 1024];             // fp16 k1_w3/k2_w3
__device__ __align__(16) __half g_Wh[(size_t)ROWS_TOT * 1024];   // 246 MB per-edge weights
// layout within a row's 1024 halves: element (i,o) at (i>>2)*128 + o*4 + (i&3)
__device__ float g_rootsum[WIDTH * WIDTH];
__device__ float g_biassum[WIDTH];

// ---------------- fused setup A: fc1 + zero agg + zero cnt ----------------
__global__ void setupA_kernel(const float* __restrict__ x,
                              const float* __restrict__ w,
                              const float* __restrict__ b) {
    int i = blockIdx.x * blockDim.x + threadIdx.x;
    if (i < N_NODES * WIDTH) {
        int n = i >> 5, c = i & 31;
        float v = fmaf(x[n], w[c], b[c]);
        g_h0[i] = v;
        g_h[i]  = v;
        g_agg[i] = 0.f;
    }
    if (i < N_NODES) { g_cnt1[i] = 0.f; g_cnt2[i] = 0.f; }
}

__global__ void count_kernel(const int* __restrict__ ei,
                             const int* __restrict__ eib) {
    int e = blockIdx.x * blockDim.x + threadIdx.x;
    if (e < E_MAIN) {
        atomicAdd(&g_cnt1[ei[E_MAIN + e]], 1.0f);
    } else if (e < E_TOT) {
        int eb = e - E_MAIN;
        atomicAdd(&g_cnt2[eib[E_BND + eb]], 1.0f);
    }
}

// ---------------- fused setup B: inv + rootsum + conv w2/w3 to fp16 -----------
__global__ void setupB_kernel(const float* __restrict__ r1, const float* __restrict__ b1,
                              const float* __restrict__ r2, const float* __restrict__ b2,
                              const float* __restrict__ w2a, const float* __restrict__ w2b,
                              const float* __restrict__ w3a, const float* __restrict__ w3b) {
    int i = blockIdx.x * blockDim.x + threadIdx.x;
    if (i < KW * 1024) {
        g_w3h[0][i] = __float2half_rn(w3a[i]);
        g_w3h[1][i] = __float2half_rn(w3b[i]);
    }
    if (i < KW * KW) {
        g_w2h[0][i] = __float2half_rn(w2a[i]);
        g_w2h[1][i] = __float2half_rn(w2b[i]);
    }
    if (i < N_NODES) {
        g_inv1[i] = 1.0f / fmaxf(g_cnt1[i], 1.0f);
        g_inv2[i] = 1.0f / fmaxf(g_cnt2[i], 1.0f);
    }
    if (i < WIDTH * WIDTH) g_rootsum[i] = r1[i] + r2[i];
    if (i < WIDTH)         g_biassum[i] = b1[i] + b2[i];
}

// ---------------- kernel MLP via HMMA ----------------
// 128 edges per block (rows r0..r0+127 in padded space), 256 threads / 8 warps.
// layer1 (K=6) by FMA -> fp16 smem tile As[128][64]; layer2 by mma.m16n8k16
// against w2^T tile (XOR-swizzled); fused bias+relu epilogue -> g_khid.
__global__ void __launch_bounds__(256) kermlp_kernel(
    const float* __restrict__ ea1, const float* __restrict__ ea2,
    const float* __restrict__ k1w1, const float* __restrict__ k1b1, const float* __restrict__ k1b2,
    const float* __restrict__ k2w1, const float* __restrict__ k2b1, const float* __restrict__ k2b2)
{
    __shared__ float sea[128 * 6];
    __shared__ float sw1[6 * 64];
    __shared__ float sb1[64];
    __shared__ float sb2[64];
    __shared__ __half As[128 * 72];   // [edge][h1-k], stride 72
    __shared__ __half Bs[64 * 72];    // [n][k ^ swz], stride 72

    int t = threadIdx.x;
    int r0 = blockIdx.x * 128;
    int set = (r0 >= E_PAD) ? 1 : 0;
    int ebase = set ? (r0 - E_PAD) : r0;
    int valid = set ? E_BND : E_MAIN;
    const float* ea = set ? ea2 : ea1;
    const float* w1 = set ? k2w1 : k1w1;
    const float* b1 = set ? k2b1 : k1b1;
    const float* b2 = set ? k2b2 : k1b2;

    // FIX (R8 bug): strided load — 384 elements, 256 threads
    for (int i = t; i < 6 * 64; i += 256) sw1[i] = w1[i];
    if (t < 64) { sb1[t] = b1[t]; sb2[t] = b2[t]; }
    #pragma unroll
    for (int i = 0; i < 3; i++) {
        int idx = t + 256 * i;                 // 0..767
        int e = idx / 6, c = idx - e * 6;
        int eg = ebase + e;
        sea[idx] = (eg < valid) ? ea[(size_t)eg * 6 + c] : 0.f;
    }
    // w2^T tile: g_w2h[set] is [k=64][n=64] row-major; store Bs[n][k^swz]
    #pragma unroll
    for (int i = 0; i < 2; i++) {
        int idx = t + 256 * i;                 // 0..511
        int k = idx >> 3, n8 = idx & 7;
        uint4 v = *(const uint4*)&g_w2h[set][k * 64 + n8 * 8];
        const __half* hv = (const __half*)&v;
        int ksw = k ^ (n8 * 8);
        #pragma unroll
        for (int j = 0; j < 8; j++)
            Bs[(n8 * 8 + j) * 72 + ksw] = hv[j];
    }
    __syncthreads();

    // layer1: thread t -> edge t>>1, outputs (t&1)*32..+31
    {
        int e = t >> 1, ob = (t & 1) * 32;
        float a0 = sea[e * 6 + 0], a1 = sea[e * 6 + 1], a2 = sea[e * 6 + 2];
        float a3 = sea[e * 6 + 3], a4 = sea[e * 6 + 4], a5 = sea[e * 6 + 5];
        #pragma unroll
        for (int o = 0; o < 32; o += 2) {
            int oc = ob + o;
            float v0 = sb1[oc], v1 = sb1[oc + 1];
            v0 = fmaf(a0, sw1[0 * 64 + oc], v0); v1 = fmaf(a0, sw1[0 * 64 + oc + 1], v1);
            v0 = fmaf(a1, sw1[1 * 64 + oc], v0); v1 = fmaf(a1, sw1[1 * 64 + oc + 1], v1);
            v0 = fmaf(a2, sw1[2 * 64 + oc], v0); v1 = fmaf(a2, sw1[2 * 64 + oc + 1], v1);
            v0 = fmaf(a3, sw1[3 * 64 + oc], v0); v1 = fmaf(a3, sw1[3 * 64 + oc + 1], v1);
            v0 = fmaf(a4, sw1[4 * 64 + oc], v0); v1 = fmaf(a4, sw1[4 * 64 + oc + 1], v1);
            v0 = fmaf(a5, sw1[5 * 64 + oc], v0); v1 = fmaf(a5, sw1[5 * 64 + oc + 1], v1);
            __half2 p = __floats2half2_rn(fmaxf(v0, 0.f), fmaxf(v1, 0.f));
            *(__half2*)&As[e * 72 + oc] = p;
        }
    }
    __syncthreads();

    // layer2: warp w owns rows wr..wr+15, all 64 cols
    int w = t >> 5, lane = t & 31;
    int wr = w * 16;
    int qrow = lane >> 2;
    int qk2  = (lane & 3) * 2;

    float acc[8][4];
    #pragma unroll
    for (int cf = 0; cf < 8; cf++)
        #pragma unroll
        for (int v = 0; v < 4; v++) acc[cf][v] = 0.f;

    #pragma unroll
    for (int ks = 0; ks < 4; ks++) {
        int k0 = ks * 16;
        const __half* ap = &As[(wr + qrow) * 72 + k0 + qk2];
        uint32_t a0 = *(const uint32_t*)ap;
        uint32_t a1 = *(const uint32_t*)(ap + 8 * 72);
        uint32_t a2 = *(const uint32_t*)(ap + 8);
        uint32_t a3 = *(const uint32_t*)(ap + 8 * 72 + 8);
        #pragma unroll
        for (int cf = 0; cf < 8; cf++) {
            int n = cf * 8 + qrow;
            int xorv = cf * 8;                 // ((n>>3)&7)*8, qrow<8
            uint32_t b0 = *(const uint32_t*)&Bs[n * 72 + ((k0 + qk2) ^ xorv)];
            uint32_t b1 = *(const uint32_t*)&Bs[n * 72 + ((k0 + qk2 + 8) ^ xorv)];
            asm volatile(
                "mma.sync.aligned.m16n8k16.row.col.f32.f16.f16.f32 "
                "{%0,%1,%2,%3}, {%4,%5,%6,%7}, {%8,%9}, {%0,%1,%2,%3};"
                : "+f"(acc[cf][0]), "+f"(acc[cf][1]), "+f"(acc[cf][2]), "+f"(acc[cf][3])
                : "r"(a0), "r"(a1), "r"(a2), "r"(a3), "r"(b0), "r"(b1));
        }
    }

    // epilogue: bias + relu -> fp16 khid
    int row0 = r0 + wr + qrow;
    #pragma unroll
    for (int cf = 0; cf < 8; cf++) {
        int col = cf * 8 + (lane & 3) * 2;
        float bb0 = sb2[col], bb1 = sb2[col + 1];
        __half2 p0 = __floats2half2_rn(fmaxf(acc[cf][0] + bb0, 0.f),
                                       fmaxf(acc[cf][1] + bb1, 0.f));
        __half2 p1 = __floats2half2_rn(fmaxf(acc[cf][2] + bb0, 0.f),
                                       fmaxf(acc[cf][3] + bb1, 0.f));
        *(__half2*)&g_khid[(size_t)row0 * 64 + col]       = p0;
        *(__half2*)&g_khid[(size_t)(row0 + 8) * 64 + col] = p1;
    }
}

// ---------------- W = khid @ w3 + b3 via HMMA m16n8k16 ----------------
__global__ void __launch_bounds__(256) w3gemm_kernel(
    const float* __restrict__ b3a, const float* __restrict__ b3b)
{
    __shared__ union {
        struct {
            __half A[128 * 72];   // [row][k], stride 72 halves
            __half B[128 * 72];   // [n][k^swz], stride 72 halves
        } in;
        __half E[128 * 136];      // epilogue staging, stride 136 halves
    } sm;
    __shared__ float sbias[128];

    int rb = blockIdx.x, cb = blockIdx.y;
    size_t r0 = (size_t)rb * 128;
    int set = (r0 >= (size_t)E_PAD) ? 1 : 0;
    const float* b3 = set ? b3b : b3a;
    int t = threadIdx.x;

    if (t < 128) sbias[t] = b3[cb * 128 + t];

    const __half* Ag = g_khid + r0 * 64;
    #pragma unroll
    for (int i = 0; i < 4; i++) {
        int idx = t + 256 * i;
        int r = idx >> 3, c8 = idx & 7;
        *(uint4*)&sm.in.A[r * 72 + c8 * 8] = *(const uint4*)&Ag[r * 64 + c8 * 8];
    }
    const __half* Bg = g_w3h[set] + cb * 128;
    #pragma unroll
    for (int i = 0; i < 4; i++) {
        int idx = t + 256 * i;
        int k = idx >> 4, n8 = idx & 15;
        uint4 v = *(const uint4*)&Bg[(size_t)k * 1024 + n8 * 8];
        const __half* hv = (const __half*)&v;
        int ksw = k ^ ((n8 & 7) * 8);
        #pragma unroll
        for (int j = 0; j < 8; j++)
            sm.in.B[(n8 * 8 + j) * 72 + ksw] = hv[j];
    }
    __syncthreads();

    int w = t >> 5, lane = t & 31;
    int wr = (w & 1) * 64;
    int wc = (w >> 1) * 32;
    int qrow = lane >> 2;
    int qk2  = (lane & 3) * 2;

    float acc[4][4][4];
    #pragma unroll
    for (int rf = 0; rf < 4; rf++)
        #pragma unroll
        for (int cf = 0; cf < 4; cf++)
            #pragma unroll
            for (int v = 0; v < 4; v++) acc[rf][cf][v] = 0.f;

    #pragma unroll
    for (int ks = 0; ks < 4; ks++) {
        int k0 = ks * 16;
        uint32_t a[4][4], b[4][2];
        #pragma unroll
        for (int rf = 0; rf < 4; rf++) {
            const __half* ap = &sm.in.A[(wr + rf * 16 + qrow) * 72 + k0 + qk2];
            a[rf][0] = *(const uint32_t*)ap;
            a[rf][1] = *(const uint32_t*)(ap + 8 * 72);
            a[rf][2] = *(const uint32_t*)(ap + 8);
            a[rf][3] = *(const uint32_t*)(ap + 8 * 72 + 8);
        }
        #pragma unroll
        for (int cf = 0; cf < 4; cf++) {
            int n = wc + cf * 8 + qrow;
            int xorv = ((n >> 3) & 7) * 8;
            b[cf][0] = *(const uint32_t*)&sm.in.B[n * 72 + ((k0 + qk2) ^ xorv)];
            b[cf][1] = *(const uint32_t*)&sm.in.B[n * 72 + ((k0 + qk2 + 8) ^ xorv)];
        }
        #pragma unroll
        for (int rf = 0; rf < 4; rf++)
            #pragma unroll
            for (int cf = 0; cf < 4; cf++)
                asm volatile(
                    "mma.sync.aligned.m16n8k16.row.col.f32.f16.f16.f32 "
                    "{%0,%1,%2,%3}, {%4,%5,%6,%7}, {%8,%9}, {%0,%1,%2,%3};"
                    : "+f"(acc[rf][cf][0]), "+f"(acc[rf][cf][1]),
                      "+f"(acc[rf][cf][2]), "+f"(acc[rf][cf][3])
                    : "r"(a[rf][0]), "r"(a[rf][1]), "r"(a[rf][2]), "r"(a[rf][3]),
                      "r"(b[cf][0]), "r"(b[cf][1]));
    }
    __syncthreads();

    #pragma unroll
    for (int rf = 0; rf < 4; rf++) {
        int row = wr + rf * 16 + qrow;
        #pragma unroll
        for (int cf = 0; cf < 4; cf++) {
            int cbl = wc + cf * 8 + (lane & 3) * 2;
            int dest = (cbl & 31) * 4 + (cbl >> 5);
            sm.E[row * 136 + dest]           = __float2half_rn(acc[rf][cf][0] + sbias[cbl]);
            sm.E[row * 136 + dest + 4]       = __float2half_rn(acc[rf][cf][1] + sbias[cbl + 1]);
            sm.E[(row + 8) * 136 + dest]     = __float2half_rn(acc[rf][cf][2] + sbias[cbl]);
            sm.E[(row + 8) * 136 + dest + 4] = __float2half_rn(acc[rf][cf][3] + sbias[cbl + 1]);
        }
    }
    __syncthreads();

    #pragma unroll
    for (int i = 0; i < 8; i++) {
        int idx = t + 256 * i;
        int r = idx >> 4, c8 = idx & 15;
        *(uint4*)&g_Wh[(r0 + r) * 1024 + cb * 128 + c8 * 8] =
            *(const uint4*)&sm.E[r * 136 + c8 * 8];
    }
}

// ---------------- per-edge message: 2 edges per warp ----------------
__global__ void __launch_bounds__(256) edge_msg_kernel(const int* __restrict__ ei,
                                                       const int* __restrict__ eib)
{
    int w = (blockIdx.x * blockDim.x + threadIdx.x) >> 5;
    int lane = threadIdx.x & 31;
    int e0 = 2 * w;
    if (e0 >= E_TOT) return;

    int src0, dst0, src1, dst1; size_t wr0, wr1; float sc0, sc1;
    if (e0 < E_MAIN) {
        src0 = ei[e0];     dst0 = ei[E_MAIN + e0];
        src1 = ei[e0 + 1]; dst1 = ei[E_MAIN + e0 + 1];
        wr0 = (size_t)e0; wr1 = (size_t)e0 + 1;
        sc0 = g_inv1[dst0]; sc1 = g_inv1[dst1];
    } else {
        int eb = e0 - E_MAIN;
        src0 = eib[eb];     dst0 = eib[E_BND + eb];
        src1 = eib[eb + 1]; dst1 = eib[E_BND + eb + 1];
        wr0 = (size_t)E_PAD + eb; wr1 = (size_t)E_PAD + eb + 1;
        sc0 = g_inv2[dst0]; sc1 = g_inv2[dst1];
    }

    float hv0 = g_h[src0 * WIDTH + lane];
    float hv1 = g_h[src1 * WIDTH + lane];
    const __half* __restrict__ W0 = g_Wh + wr0 * 1024;
    const __half* __restrict__ W1 = g_Wh + wr1 * 1024;
    float m0 = 0.f, m1 = 0.f;
    #pragma unroll
    for (int j = 0; j < 8; j++) {
        uint2 v0 = *(const uint2*)(W0 + (size_t)j * 128 + lane * 4);
        uint2 v1 = *(const uint2*)(W1 + (size_t)j * 128 + lane * 4);
        float2 a0 = __half22float2(*reinterpret_cast<const __half2*>(&v0.x));
        float2 a1 = __half22float2(*reinterpret_cast<const __half2*>(&v0.y));
        float2 b0 = __half22float2(*reinterpret_cast<const __half2*>(&v1.x));
        float2 b1 = __half22float2(*reinterpret_cast<const __half2*>(&v1.y));
        float h00 = __shfl_sync(0xffffffffu, hv0, 4 * j + 0);
        float h01 = __shfl_sync(0xffffffffu, hv0, 4 * j + 1);
        float h02 = __shfl_sync(0xffffffffu, hv0, 4 * j + 2);
        float h03 = __shfl_sync(0xffffffffu, hv0, 4 * j + 3);
        float h10 = __shfl_sync(0xffffffffu, hv1, 4 * j + 0);
        float h11 = __shfl_sync(0xffffffffu, hv1, 4 * j + 1);
        float h12 = __shfl_sync(0xffffffffu, hv1, 4 * j + 2);
        float h13 = __shfl_sync(0xffffffffu, hv1, 4 * j + 3);
        m0 = fmaf(a0.x, h00, m0); m0 = fmaf(a0.y, h01, m0);
        m0 = fmaf(a1.x, h02, m0); m0 = fmaf(a1.y, h03, m0);
        m1 = fmaf(b0.x, h10, m1); m1 = fmaf(b0.y, h11, m1);
        m1 = fmaf(b1.x, h12, m1); m1 = fmaf(b1.y, h13, m1);
    }
    atomicAdd(&g_agg[dst0 * WIDTH + lane], m0 * sc0);
    atomicAdd(&g_agg[dst1 * WIDTH + lane], m1 * sc1);
}

// ---------------- node update (consumes + re-zeroes agg; optionally fc2) ------
__global__ void __launch_bounds__(256) node_update_kernel(int last,
                                                          const float* __restrict__ fc2w,
                                                          const float* __restrict__ fc2b,
                                                          float* __restrict__ out) {
    int n = (blockIdx.x * blockDim.x + threadIdx.x) >> 5;
    int lane = threadIdx.x & 31;
    if (n >= N_NODES) return;

    float hv  = g_h[n * WIDTH + lane];
    float acc = g_agg[n * WIDTH + lane] + g_biassum[lane];
    g_agg[n * WIDTH + lane] = 0.f;
    #pragma unroll
    for (int i = 0; i < 32; i++) {
        float hi = __shfl_sync(0xffffffffu, hv, i);
        acc = fmaf(hi, g_rootsum[i * 32 + lane], acc);
    }
    float hnew = fmaxf(acc, 0.f) + g_h0[n * WIDTH + lane];
    g_h[n * WIDTH + lane] = hnew;

    if (last) {
        float v = hnew * fc2w[lane];
        #pragma unroll
        for (int off = 16; off > 0; off >>= 1)
            v += __shfl_xor_sync(0xffffffffu, v, off);
        if (lane == 0) out[n] = v + fc2b[0];
    }
}

// ---------------- host orchestration ----------------
extern "C" void kernel_launch(void* const* d_in, const int* in_sizes, int n_in,
                              void* d_out, int out_size) {
    const float* x    = (const float*)d_in[0];
    const int*   ei   = (const int*)  d_in[1];
    const float* ea   = (const float*)d_in[2];
    const int*   eib  = (const int*)  d_in[3];
    const float* eab  = (const float*)d_in[4];
    const float* fc1w = (const float*)d_in[5];
    const float* fc1b = (const float*)d_in[6];
    const float* fc2w = (const float*)d_in[7];
    const float* fc2b = (const float*)d_in[8];
    const float* k1w1 = (const float*)d_in[9];
    const float* k1b1 = (const float*)d_in[10];
    const float* k1w2 = (const float*)d_in[11];
    const float* k1b2 = (const float*)d_in[12];
    const float* k1w3 = (const float*)d_in[13];
    const float* k1b3 = (const float*)d_in[14];
    const float* root1= (const float*)d_in[15];
    const float* bias1= (const float*)d_in[16];
    const float* k2w1 = (const float*)d_in[17];
    const float* k2b1 = (const float*)d_in[18];
    const float* k2w2 = (const float*)d_in[19];
    const float* k2b2 = (const float*)d_in[20];
    const float* k2w3 = (const float*)d_in[21];
    const float* k2b3 = (const float*)d_in[22];
    const float* root2= (const float*)d_in[23];
    const float* bias2= (const float*)d_in[24];
    float* out = (float*)d_out;

    // ncu profiles launch #4 -> kermlp_kernel
    setupA_kernel<<<(N_NODES * WIDTH + 255) / 256, 256>>>(x, fc1w, fc1b);      // 1
    count_kernel<<<(E_TOT + 255) / 256, 256>>>(ei, eib);                       // 2
    setupB_kernel<<<(KW * 1024 + 255) / 256, 256>>>(root1, bias1, root2, bias2,
                                                    k1w2, k2w2, k1w3, k2w3);   // 3
    kermlp_kernel<<<ROWS_TOT / 128, 256>>>(ea, eab,
                                           k1w1, k1b1, k1b2,
                                           k2w1, k2b1, k2b2);                  // 4
    dim3 ggrid(ROWS_TOT / 128, 1024 / 128);
    w3gemm_kernel<<<ggrid, 256>>>(k1b3, k2b3);                                 // 5

    for (int d = 0; d < DEPTH; d++) {
        edge_msg_kernel<<<(E_TOT / 2 * 32 + 255) / 256, 256>>>(ei, eib);       // 6 on d=0
        node_update_kernel<<<(N_NODES * 32 + 255) / 256, 256>>>(
            d == DEPTH - 1 ? 1 : 0, fc2w, fc2b, out);
    }
}

// round 10
// speedup vs baseline: 2.5923x; 1.0053x over previous
#include <cuda_runtime.h>
#include <cuda_fp16.h>
#include <stdint.h>

// ---------------- problem constants (fixed by dataset) ----------------
#define N_NODES 20000
#define E_MAIN  100000
#define E_BND   20000
#define E_TOT   (E_MAIN + E_BND)
#define E_PAD   100096            // E_MAIN rounded up to 128
#define EB_PAD  20096             // E_BND  rounded up to 128
#define ROWS_TOT (E_PAD + EB_PAD) // 120192, multiple of 128
#define WIDTH   32
#define KW      64
#define DEPTH   4

// ---------------- device scratch (no allocations allowed) ----------------
__device__ float g_h0[N_NODES * WIDTH];
__device__ float g_h [N_NODES * WIDTH];
__device__ float g_agg[N_NODES * WIDTH];
__device__ float g_cnt1[N_NODES];
__device__ float g_cnt2[N_NODES];
__device__ __align__(16) __half g_khid[(size_t)ROWS_TOT * KW];   // 15.4 MB, fp16
__device__ __align__(16) __half g_w2h[2][KW * KW];               // fp16 k1_w2/k2_w2
__device__ __align__(16) __half g_w3h[2][KW * 1024];             // fp16 k1_w3/k2_w3
__device__ __align__(16) __half g_Wh[(size_t)ROWS_TOT * 1024];   // 246 MB per-edge weights
// layout within a row's 1024 halves: element (i,o) at (i>>2)*128 + o*4 + (i&3)
__device__ float g_rootsum[WIDTH * WIDTH];
__device__ float g_biassum[WIDTH];

// ---------------- setup B: rootsum + conv w2/w3 to fp16 (no deps) -------------
__global__ void setupB_kernel(const float* __restrict__ r1, const float* __restrict__ b1,
                              const float* __restrict__ r2, const float* __restrict__ b2,
                              const float* __restrict__ w2a, const float* __restrict__ w2b,
                              const float* __restrict__ w3a, const float* __restrict__ w3b) {
    int i = blockIdx.x * blockDim.x + threadIdx.x;
    if (i < KW * 1024) {
        g_w3h[0][i] = __float2half_rn(w3a[i]);
        g_w3h[1][i] = __float2half_rn(w3b[i]);
    }
    if (i < KW * KW) {
        g_w2h[0][i] = __float2half_rn(w2a[i]);
        g_w2h[1][i] = __float2half_rn(w2b[i]);
    }
    if (i < WIDTH * WIDTH) g_rootsum[i] = r1[i] + r2[i];
    if (i < WIDTH)         g_biassum[i] = b1[i] + b2[i];
}

// ---------------- setup A: fc1 + zero agg + zero cnt ----------------
__global__ void setupA_kernel(const float* __restrict__ x,
                              const float* __restrict__ w,
                              const float* __restrict__ b) {
    int i = blockIdx.x * blockDim.x + threadIdx.x;
    if (i < N_NODES * WIDTH) {
        int n = i >> 5, c = i & 31;
        float v = fmaf(x[n], w[c], b[c]);
        g_h0[i] = v;
        g_h[i]  = v;
        g_agg[i] = 0.f;
    }
    if (i < N_NODES) { g_cnt1[i] = 0.f; g_cnt2[i] = 0.f; }
}

__global__ void count_kernel(const int* __restrict__ ei,
                             const int* __restrict__ eib) {
    int e = blockIdx.x * blockDim.x + threadIdx.x;
    if (e < E_MAIN) {
        atomicAdd(&g_cnt1[ei[E_MAIN + e]], 1.0f);
    } else if (e < E_TOT) {
        int eb = e - E_MAIN;
        atomicAdd(&g_cnt2[eib[E_BND + eb]], 1.0f);
    }
}

// ---------------- kernel MLP via HMMA ----------------
__global__ void __launch_bounds__(256) kermlp_kernel(
    const float* __restrict__ ea1, const float* __restrict__ ea2,
    const float* __restrict__ k1w1, const float* __restrict__ k1b1, const float* __restrict__ k1b2,
    const float* __restrict__ k2w1, const float* __restrict__ k2b1, const float* __restrict__ k2b2)
{
    __shared__ float sea[128 * 6];
    __shared__ float sw1[6 * 64];
    __shared__ float sb1[64];
    __shared__ float sb2[64];
    __shared__ __half As[128 * 72];   // [edge][h1-k], stride 72
    __shared__ __half Bs[64 * 72];    // [n][k ^ swz], stride 72

    int t = threadIdx.x;
    int r0 = blockIdx.x * 128;
    int set = (r0 >= E_PAD) ? 1 : 0;
    int ebase = set ? (r0 - E_PAD) : r0;
    int valid = set ? E_BND : E_MAIN;
    const float* ea = set ? ea2 : ea1;
    const float* w1 = set ? k2w1 : k1w1;
    const float* b1 = set ? k2b1 : k1b1;
    const float* b2 = set ? k2b2 : k1b2;

    for (int i = t; i < 6 * 64; i += 256) sw1[i] = w1[i];
    if (t < 64) { sb1[t] = b1[t]; sb2[t] = b2[t]; }
    #pragma unroll
    for (int i = 0; i < 3; i++) {
        int idx = t + 256 * i;                 // 0..767
        int e = idx / 6, c = idx - e * 6;
        int eg = ebase + e;
        sea[idx] = (eg < valid) ? ea[(size_t)eg * 6 + c] : 0.f;
    }
    // w2^T tile: g_w2h[set] is [k=64][n=64] row-major; store Bs[n][k^swz]
    #pragma unroll
    for (int i = 0; i < 2; i++) {
        int idx = t + 256 * i;                 // 0..511
        int k = idx >> 3, n8 = idx & 7;
        uint4 v = *(const uint4*)&g_w2h[set][k * 64 + n8 * 8];
        const __half* hv = (const __half*)&v;
        int ksw = k ^ (n8 * 8);
        #pragma unroll
        for (int j = 0; j < 8; j++)
            Bs[(n8 * 8 + j) * 72 + ksw] = hv[j];
    }
    __syncthreads();

    // layer1: thread t -> edge t>>1, outputs (t&1)*32..+31
    {
        int e = t >> 1, ob = (t & 1) * 32;
        float a0 = sea[e * 6 + 0], a1 = sea[e * 6 + 1], a2 = sea[e * 6 + 2];
        float a3 = sea[e * 6 + 3], a4 = sea[e * 6 + 4], a5 = sea[e * 6 + 5];
        #pragma unroll
        for (int o = 0; o < 32; o += 2) {
            int oc = ob + o;
            float v0 = sb1[oc], v1 = sb1[oc + 1];
            v0 = fmaf(a0, sw1[0 * 64 + oc], v0); v1 = fmaf(a0, sw1[0 * 64 + oc + 1], v1);
            v0 = fmaf(a1, sw1[1 * 64 + oc], v0); v1 = fmaf(a1, sw1[1 * 64 + oc + 1], v1);
            v0 = fmaf(a2, sw1[2 * 64 + oc], v0); v1 = fmaf(a2, sw1[2 * 64 + oc + 1], v1);
            v0 = fmaf(a3, sw1[3 * 64 + oc], v0); v1 = fmaf(a3, sw1[3 * 64 + oc + 1], v1);
            v0 = fmaf(a4, sw1[4 * 64 + oc], v0); v1 = fmaf(a4, sw1[4 * 64 + oc + 1], v1);
            v0 = fmaf(a5, sw1[5 * 64 + oc], v0); v1 = fmaf(a5, sw1[5 * 64 + oc + 1], v1);
            __half2 p = __floats2half2_rn(fmaxf(v0, 0.f), fmaxf(v1, 0.f));
            *(__half2*)&As[e * 72 + oc] = p;
        }
    }
    __syncthreads();

    // layer2: warp w owns rows wr..wr+15, all 64 cols
    int w = t >> 5, lane = t & 31;
    int wr = w * 16;
    int qrow = lane >> 2;
    int qk2  = (lane & 3) * 2;

    float acc[8][4];
    #pragma unroll
    for (int cf = 0; cf < 8; cf++)
        #pragma unroll
        for (int v = 0; v < 4; v++) acc[cf][v] = 0.f;

    #pragma unroll
    for (int ks = 0; ks < 4; ks++) {
        int k0 = ks * 16;
        const __half* ap = &As[(wr + qrow) * 72 + k0 + qk2];
        uint32_t a0 = *(const uint32_t*)ap;
        uint32_t a1 = *(const uint32_t*)(ap + 8 * 72);
        uint32_t a2 = *(const uint32_t*)(ap + 8);
        uint32_t a3 = *(const uint32_t*)(ap + 8 * 72 + 8);
        #pragma unroll
        for (int cf = 0; cf < 8; cf++) {
            int n = cf * 8 + qrow;
            int xorv = cf * 8;
            uint32_t b0 = *(const uint32_t*)&Bs[n * 72 + ((k0 + qk2) ^ xorv)];
            uint32_t b1 = *(const uint32_t*)&Bs[n * 72 + ((k0 + qk2 + 8) ^ xorv)];
            asm volatile(
                "mma.sync.aligned.m16n8k16.row.col.f32.f16.f16.f32 "
                "{%0,%1,%2,%3}, {%4,%5,%6,%7}, {%8,%9}, {%0,%1,%2,%3};"
                : "+f"(acc[cf][0]), "+f"(acc[cf][1]), "+f"(acc[cf][2]), "+f"(acc[cf][3])
                : "r"(a0), "r"(a1), "r"(a2), "r"(a3), "r"(b0), "r"(b1));
        }
    }

    // epilogue: bias + relu -> fp16 khid
    int row0 = r0 + wr + qrow;
    #pragma unroll
    for (int cf = 0; cf < 8; cf++) {
        int col = cf * 8 + (lane & 3) * 2;
        float bb0 = sb2[col], bb1 = sb2[col + 1];
        __half2 p0 = __floats2half2_rn(fmaxf(acc[cf][0] + bb0, 0.f),
                                       fmaxf(acc[cf][1] + bb1, 0.f));
        __half2 p1 = __floats2half2_rn(fmaxf(acc[cf][2] + bb0, 0.f),
                                       fmaxf(acc[cf][3] + bb1, 0.f));
        *(__half2*)&g_khid[(size_t)row0 * 64 + col]       = p0;
        *(__half2*)&g_khid[(size_t)(row0 + 8) * 64 + col] = p1;
    }
}

// ---------------- W = khid @ w3 + b3 via HMMA m16n8k16 ----------------
__global__ void __launch_bounds__(256) w3gemm_kernel(
    const float* __restrict__ b3a, const float* __restrict__ b3b)
{
    __shared__ union {
        struct {
            __half A[128 * 72];   // [row][k], stride 72 halves
            __half B[128 * 72];   // [n][k^swz], stride 72 halves
        } in;
        __half E[128 * 136];      // epilogue staging, stride 136 halves
    } sm;
    __shared__ float sbias[128];

    int rb = blockIdx.x, cb = blockIdx.y;
    size_t r0 = (size_t)rb * 128;
    int set = (r0 >= (size_t)E_PAD) ? 1 : 0;
    const float* b3 = set ? b3b : b3a;
    int t = threadIdx.x;

    if (t < 128) sbias[t] = b3[cb * 128 + t];

    const __half* Ag = g_khid + r0 * 64;
    #pragma unroll
    for (int i = 0; i < 4; i++) {
        int idx = t + 256 * i;
        int r = idx >> 3, c8 = idx & 7;
        *(uint4*)&sm.in.A[r * 72 + c8 * 8] = *(const uint4*)&Ag[r * 64 + c8 * 8];
    }
    const __half* Bg = g_w3h[set] + cb * 128;
    #pragma unroll
    for (int i = 0; i < 4; i++) {
        int idx = t + 256 * i;
        int k = idx >> 4, n8 = idx & 15;
        uint4 v = *(const uint4*)&Bg[(size_t)k * 1024 + n8 * 8];
        const __half* hv = (const __half*)&v;
        int ksw = k ^ ((n8 & 7) * 8);
        #pragma unroll
        for (int j = 0; j < 8; j++)
            sm.in.B[(n8 * 8 + j) * 72 + ksw] = hv[j];
    }
    __syncthreads();

    int w = t >> 5, lane = t & 31;
    int wr = (w & 1) * 64;
    int wc = (w >> 1) * 32;
    int qrow = lane >> 2;
    int qk2  = (lane & 3) * 2;

    float acc[4][4][4];
    #pragma unroll
    for (int rf = 0; rf < 4; rf++)
        #pragma unroll
        for (int cf = 0; cf < 4; cf++)
            #pragma unroll
            for (int v = 0; v < 4; v++) acc[rf][cf][v] = 0.f;

    #pragma unroll
    for (int ks = 0; ks < 4; ks++) {
        int k0 = ks * 16;
        uint32_t a[4][4], b[4][2];
        #pragma unroll
        for (int rf = 0; rf < 4; rf++) {
            const __half* ap = &sm.in.A[(wr + rf * 16 + qrow) * 72 + k0 + qk2];
            a[rf][0] = *(const uint32_t*)ap;
            a[rf][1] = *(const uint32_t*)(ap + 8 * 72);
            a[rf][2] = *(const uint32_t*)(ap + 8);
            a[rf][3] = *(const uint32_t*)(ap + 8 * 72 + 8);
        }
        #pragma unroll
        for (int cf = 0; cf < 4; cf++) {
            int n = wc + cf * 8 + qrow;
            int xorv = ((n >> 3) & 7) * 8;
            b[cf][0] = *(const uint32_t*)&sm.in.B[n * 72 + ((k0 + qk2) ^ xorv)];
            b[cf][1] = *(const uint32_t*)&sm.in.B[n * 72 + ((k0 + qk2 + 8) ^ xorv)];
        }
        #pragma unroll
        for (int rf = 0; rf < 4; rf++)
            #pragma unroll
            for (int cf = 0; cf < 4; cf++)
                asm volatile(
                    "mma.sync.aligned.m16n8k16.row.col.f32.f16.f16.f32 "
                    "{%0,%1,%2,%3}, {%4,%5,%6,%7}, {%8,%9}, {%0,%1,%2,%3};"
                    : "+f"(acc[rf][cf][0]), "+f"(acc[rf][cf][1]),
                      "+f"(acc[rf][cf][2]), "+f"(acc[rf][cf][3])
                    : "r"(a[rf][0]), "r"(a[rf][1]), "r"(a[rf][2]), "r"(a[rf][3]),
                      "r"(b[cf][0]), "r"(b[cf][1]));
    }
    __syncthreads();

    #pragma unroll
    for (int rf = 0; rf < 4; rf++) {
        int row = wr + rf * 16 + qrow;
        #pragma unroll
        for (int cf = 0; cf < 4; cf++) {
            int cbl = wc + cf * 8 + (lane & 3) * 2;
            int dest = (cbl & 31) * 4 + (cbl >> 5);
            sm.E[row * 136 + dest]           = __float2half_rn(acc[rf][cf][0] + sbias[cbl]);
            sm.E[row * 136 + dest + 4]       = __float2half_rn(acc[rf][cf][1] + sbias[cbl + 1]);
            sm.E[(row + 8) * 136 + dest]     = __float2half_rn(acc[rf][cf][2] + sbias[cbl]);
            sm.E[(row + 8) * 136 + dest + 4] = __float2half_rn(acc[rf][cf][3] + sbias[cbl + 1]);
        }
    }
    __syncthreads();

    #pragma unroll
    for (int i = 0; i < 8; i++) {
        int idx = t + 256 * i;
        int r = idx >> 4, c8 = idx & 15;
        *(uint4*)&g_Wh[(r0 + r) * 1024 + cb * 128 + c8 * 8] =
            *(const uint4*)&sm.E[r * 136 + c8 * 8];
    }
}

// ---------------- per-edge message: 1 warp/edge, uint4 loads ----------------
// lane l: ib = l>>4 (i-block parity), op = l&15 (channel pair 2op, 2op+1).
// 4 x 16B loads per lane; cross-parity combine via shfl_xor(16).
__global__ void __launch_bounds__(256) edge_msg_kernel(const int* __restrict__ ei,
                                                       const int* __restrict__ eib)
{
    int e = (blockIdx.x * blockDim.x + threadIdx.x) >> 5;
    int lane = threadIdx.x & 31;
    if (e >= E_TOT) return;

    int src, dst; size_t wrow; float cnt;
    if (e < E_MAIN) {
        src = ei[e]; dst = ei[E_MAIN + e];
        wrow = (size_t)e;
        cnt = g_cnt1[dst];
    } else {
        int eb = e - E_MAIN;
        src = eib[eb]; dst = eib[E_BND + eb];
        wrow = (size_t)E_PAD + eb;
        cnt = g_cnt2[dst];
    }
    float scale = 1.0f / fmaxf(cnt, 1.0f);

    float hv = g_h[src * WIDTH + lane];
    const __half* __restrict__ Wp = g_Wh + wrow * 1024;
    int ib = lane >> 4;                // 0/1
    int op = lane & 15;                // channel pair

    float m0 = 0.f, m1 = 0.f;          // channels 2op, 2op+1
    #pragma unroll
    for (int jj = 0; jj < 4; jj++) {
        int ibk = jj * 2 + ib;         // i-block 0..7 (4 i's each)
        uint4 v = *(const uint4*)(Wp + (size_t)ibk * 128 + op * 8);
        float2 c0a = __half22float2(*reinterpret_cast<const __half2*>(&v.x)); // o=2op, i+0,1
        float2 c0b = __half22float2(*reinterpret_cast<const __half2*>(&v.y)); // o=2op, i+2,3
        float2 c1a = __half22float2(*reinterpret_cast<const __half2*>(&v.z)); // o=2op+1, i+0,1
        float2 c1b = __half22float2(*reinterpret_cast<const __half2*>(&v.w)); // o=2op+1, i+2,3
        float h0 = __shfl_sync(0xffffffffu, hv, ibk * 4 + 0);
        float h1 = __shfl_sync(0xffffffffu, hv, ibk * 4 + 1);
        float h2 = __shfl_sync(0xffffffffu, hv, ibk * 4 + 2);
        float h3 = __shfl_sync(0xffffffffu, hv, ibk * 4 + 3);
        m0 = fmaf(c0a.x, h0, m0); m0 = fmaf(c0a.y, h1, m0);
        m0 = fmaf(c0b.x, h2, m0); m0 = fmaf(c0b.y, h3, m0);
        m1 = fmaf(c1a.x, h0, m1); m1 = fmaf(c1a.y, h1, m1);
        m1 = fmaf(c1b.x, h2, m1); m1 = fmaf(c1b.y, h3, m1);
    }
    // combine the two i-block parities
    m0 += __shfl_xor_sync(0xffffffffu, m0, 16);
    m1 += __shfl_xor_sync(0xffffffffu, m1, 16);

    // lanes 0..15 write channel 2op, lanes 16..31 write channel 2op+1
    int ch = op * 2 + ib;
    float mv = ib ? m1 : m0;
    atomicAdd(&g_agg[dst * WIDTH + ch], mv * scale);
}

// ---------------- node update (consumes + re-zeroes agg; optionally fc2) ------
__global__ void __launch_bounds__(256) node_update_kernel(int last,
                                                          const float* __restrict__ fc2w,
                                                          const float* __restrict__ fc2b,
                                                          float* __restrict__ out) {
    int n = (blockIdx.x * blockDim.x + threadIdx.x) >> 5;
    int lane = threadIdx.x & 31;
    if (n >= N_NODES) return;

    float hv  = g_h[n * WIDTH + lane];
    float acc = g_agg[n * WIDTH + lane] + g_biassum[lane];
    g_agg[n * WIDTH + lane] = 0.f;
    #pragma unroll
    for (int i = 0; i < 32; i++) {
        float hi = __shfl_sync(0xffffffffu, hv, i);
        acc = fmaf(hi, g_rootsum[i * 32 + lane], acc);
    }
    float hnew = fmaxf(acc, 0.f) + g_h0[n * WIDTH + lane];
    g_h[n * WIDTH + lane] = hnew;

    if (last) {
        float v = hnew * fc2w[lane];
        #pragma unroll
        for (int off = 16; off > 0; off >>= 1)
            v += __shfl_xor_sync(0xffffffffu, v, off);
        if (lane == 0) out[n] = v + fc2b[0];
    }
}

// ---------------- host orchestration ----------------
extern "C" void kernel_launch(void* const* d_in, const int* in_sizes, int n_in,
                              void* d_out, int out_size) {
    const float* x    = (const float*)d_in[0];
    const int*   ei   = (const int*)  d_in[1];
    const float* ea   = (const float*)d_in[2];
    const int*   eib  = (const int*)  d_in[3];
    const float* eab  = (const float*)d_in[4];
    const float* fc1w = (const float*)d_in[5];
    const float* fc1b = (const float*)d_in[6];
    const float* fc2w = (const float*)d_in[7];
    const float* fc2b = (const float*)d_in[8];
    const float* k1w1 = (const float*)d_in[9];
    const float* k1b1 = (const float*)d_in[10];
    const float* k1w2 = (const float*)d_in[11];
    const float* k1b2 = (const float*)d_in[12];
    const float* k1w3 = (const float*)d_in[13];
    const float* k1b3 = (const float*)d_in[14];
    const float* root1= (const float*)d_in[15];
    const float* bias1= (const float*)d_in[16];
    const float* k2w1 = (const float*)d_in[17];
    const float* k2b1 = (const float*)d_in[18];
    const float* k2w2 = (const float*)d_in[19];
    const float* k2b2 = (const float*)d_in[20];
    const float* k2w3 = (const float*)d_in[21];
    const float* k2b3 = (const float*)d_in[22];
    const float* root2= (const float*)d_in[23];
    const float* bias2= (const float*)d_in[24];
    float* out = (float*)d_out;

    // ncu profiles launch #4 -> w3gemm_kernel this round
    setupB_kernel<<<(KW * 1024 + 255) / 256, 256>>>(root1, bias1, root2, bias2,
                                                    k1w2, k2w2, k1w3, k2w3);   // 1
    setupA_kernel<<<(N_NODES * WIDTH + 255) / 256, 256>>>(x, fc1w, fc1b);      // 2
    kermlp_kernel<<<ROWS_TOT / 128, 256>>>(ea, eab,
                                           k1w1, k1b1, k1b2,
                                           k2w1, k2b1, k2b2);                  // 3
    dim3 ggrid(ROWS_TOT / 128, 1024 / 128);
    w3gemm_kernel<<<ggrid, 256>>>(k1b3, k2b3);                                 // 4
    count_kernel<<<(E_TOT + 255) / 256, 256>>>(ei, eib);                       // 5

    for (int d = 0; d < DEPTH; d++) {
        edge_msg_kernel<<<(E_TOT * 32 + 255) / 256, 256>>>(ei, eib);
        node_update_kernel<<<(N_NODES * 32 + 255) / 256, 256>>>(
            d == DEPTH - 1 ? 1 : 0, fc2w, fc2b, out);
    }
}

// round 12
// speedup vs baseline: 2.9201x; 1.1264x over previous
#include <cuda_runtime.h>
#include <cuda_fp16.h>
#include <stdint.h>

// ---------------- problem constants (fixed by dataset) ----------------
#define N_NODES 20000
#define E_MAIN  100000
#define E_BND   20000
#define E_TOT   (E_MAIN + E_BND)
#define E_PAD   100096            // E_MAIN rounded up to 128
#define EB_PAD  20096             // E_BND  rounded up to 128
#define ROWS_TOT (E_PAD + EB_PAD) // 120192, multiple of 128
#define WIDTH   32
#define KW      64
#define DEPTH   4

// W row layout (1024 halves): element (i,o) at
//   p(i,o) = i*32 + ((o>>1)&3)*8 + (o>>3)*2 + (o&1)
// chosen so the m16n8k16 accumulator fragment stores 16B-contiguous.

// ---------------- device scratch (no allocations allowed) ----------------
__device__ float g_h0[N_NODES * WIDTH];
__device__ float g_h [N_NODES * WIDTH];
__device__ float g_agg[N_NODES * WIDTH];
__device__ float g_cnt1[N_NODES];
__device__ float g_cnt2[N_NODES];
__device__ __align__(16) __half g_khid[(size_t)ROWS_TOT * KW];   // 15.4 MB, fp16
__device__ __align__(16) __half g_w2h[2][KW * KW];               // fp16 k1_w2/k2_w2
__device__ __align__(16) __half g_w3h[2][KW * 1024];             // fp16 k1_w3/k2_w3
__device__ __align__(16) __half g_Wh[(size_t)ROWS_TOT * 1024];   // 246 MB per-edge weights
__device__ float g_rootsum[WIDTH * WIDTH];
__device__ float g_biassum[WIDTH];

// ---------------- setup B: rootsum + conv w2/w3 to fp16 (no deps) -------------
__global__ void setupB_kernel(const float* __restrict__ r1, const float* __restrict__ b1,
                              const float* __restrict__ r2, const float* __restrict__ b2,
                              const float* __restrict__ w2a, const float* __restrict__ w2b,
                              const float* __restrict__ w3a, const float* __restrict__ w3b) {
    int i = blockIdx.x * blockDim.x + threadIdx.x;
    if (i < KW * 1024) {
        g_w3h[0][i] = __float2half_rn(w3a[i]);
        g_w3h[1][i] = __float2half_rn(w3b[i]);
    }
    if (i < KW * KW) {
        g_w2h[0][i] = __float2half_rn(w2a[i]);
        g_w2h[1][i] = __float2half_rn(w2b[i]);
    }
    if (i < WIDTH * WIDTH) g_rootsum[i] = r1[i] + r2[i];
    if (i < WIDTH)         g_biassum[i] = b1[i] + b2[i];
}

// ---------------- setup A: fc1 + zero agg + zero cnt ----------------
__global__ void setupA_kernel(const float* __restrict__ x,
                              const float* __restrict__ w,
                              const float* __restrict__ b) {
    int i = blockIdx.x * blockDim.x + threadIdx.x;
    if (i < N_NODES * WIDTH) {
        int n = i >> 5, c = i & 31;
        float v = fmaf(x[n], w[c], b[c]);
        g_h0[i] = v;
        g_h[i]  = v;
        g_agg[i] = 0.f;
    }
    if (i < N_NODES) { g_cnt1[i] = 0.f; g_cnt2[i] = 0.f; }
}

__global__ void count_kernel(const int* __restrict__ ei,
                             const int* __restrict__ eib) {
    int e = blockIdx.x * blockDim.x + threadIdx.x;
    if (e < E_MAIN) {
        atomicAdd(&g_cnt1[ei[E_MAIN + e]], 1.0f);
    } else if (e < E_TOT) {
        int eb = e - E_MAIN;
        atomicAdd(&g_cnt2[eib[E_BND + eb]], 1.0f);
    }
}

// ---------------- kernel MLP via HMMA ----------------
__global__ void __launch_bounds__(256) kermlp_kernel(
    const float* __restrict__ ea1, const float* __restrict__ ea2,
    const float* __restrict__ k1w1, const float* __restrict__ k1b1, const float* __restrict__ k1b2,
    const float* __restrict__ k2w1, const float* __restrict__ k2b1, const float* __restrict__ k2b2)
{
    __shared__ float sea[128 * 6];
    __shared__ float sw1[6 * 64];
    __shared__ float sb1[64];
    __shared__ float sb2[64];
    __shared__ __half As[128 * 72];   // [edge][h1-k], stride 72
    __shared__ __half Bs[64 * 72];    // [n][k ^ swz], stride 72

    int t = threadIdx.x;
    int r0 = blockIdx.x * 128;
    int set = (r0 >= E_PAD) ? 1 : 0;
    int ebase = set ? (r0 - E_PAD) : r0;
    int valid = set ? E_BND : E_MAIN;
    const float* ea = set ? ea2 : ea1;
    const float* w1 = set ? k2w1 : k1w1;
    const float* b1 = set ? k2b1 : k1b1;
    const float* b2 = set ? k2b2 : k1b2;

    for (int i = t; i < 6 * 64; i += 256) sw1[i] = w1[i];
    if (t < 64) { sb1[t] = b1[t]; sb2[t] = b2[t]; }
    #pragma unroll
    for (int i = 0; i < 3; i++) {
        int idx = t + 256 * i;                 // 0..767
        int e = idx / 6, c = idx - e * 6;
        int eg = ebase + e;
        sea[idx] = (eg < valid) ? ea[(size_t)eg * 6 + c] : 0.f;
    }
    // w2^T tile: store Bs[n][k ^ (n8*8)]
    #pragma unroll
    for (int i = 0; i < 2; i++) {
        int idx = t + 256 * i;                 // 0..511
        int k = idx >> 3, n8 = idx & 7;
        uint4 v = *(const uint4*)&g_w2h[set][k * 64 + n8 * 8];
        const __half* hv = (const __half*)&v;
        int ksw = k ^ (n8 * 8);
        #pragma unroll
        for (int j = 0; j < 8; j++)
            Bs[(n8 * 8 + j) * 72 + ksw] = hv[j];
    }
    __syncthreads();

    // layer1: thread t -> edge t>>1, outputs (t&1)*32..+31
    {
        int e = t >> 1, ob = (t & 1) * 32;
        float a0 = sea[e * 6 + 0], a1 = sea[e * 6 + 1], a2 = sea[e * 6 + 2];
        float a3 = sea[e * 6 + 3], a4 = sea[e * 6 + 4], a5 = sea[e * 6 + 5];
        #pragma unroll
        for (int o = 0; o < 32; o += 2) {
            int oc = ob + o;
            float v0 = sb1[oc], v1 = sb1[oc + 1];
            v0 = fmaf(a0, sw1[0 * 64 + oc], v0); v1 = fmaf(a0, sw1[0 * 64 + oc + 1], v1);
            v0 = fmaf(a1, sw1[1 * 64 + oc], v0); v1 = fmaf(a1, sw1[1 * 64 + oc + 1], v1);
            v0 = fmaf(a2, sw1[2 * 64 + oc], v0); v1 = fmaf(a2, sw1[2 * 64 + oc + 1], v1);
            v0 = fmaf(a3, sw1[3 * 64 + oc], v0); v1 = fmaf(a3, sw1[3 * 64 + oc + 1], v1);
            v0 = fmaf(a4, sw1[4 * 64 + oc], v0); v1 = fmaf(a4, sw1[4 * 64 + oc + 1], v1);
            v0 = fmaf(a5, sw1[5 * 64 + oc], v0); v1 = fmaf(a5, sw1[5 * 64 + oc + 1], v1);
            __half2 p = __floats2half2_rn(fmaxf(v0, 0.f), fmaxf(v1, 0.f));
            *(__half2*)&As[e * 72 + oc] = p;
        }
    }
    __syncthreads();

    // layer2: warp w owns rows wr..wr+15, all 64 cols
    int w = t >> 5, lane = t & 31;
    int wr = w * 16;
    int qrow = lane >> 2;
    int qk2  = (lane & 3) * 2;

    float acc[8][4];
    #pragma unroll
    for (int cf = 0; cf < 8; cf++)
        #pragma unroll
        for (int v = 0; v < 4; v++) acc[cf][v] = 0.f;

    #pragma unroll
    for (int ks = 0; ks < 4; ks++) {
        int k0 = ks * 16;
        const __half* ap = &As[(wr + qrow) * 72 + k0 + qk2];
        uint32_t a0 = *(const uint32_t*)ap;
        uint32_t a1 = *(const uint32_t*)(ap + 8 * 72);
        uint32_t a2 = *(const uint32_t*)(ap + 8);
        uint32_t a3 = *(const uint32_t*)(ap + 8 * 72 + 8);
        #pragma unroll
        for (int cf = 0; cf < 8; cf++) {
            int n = cf * 8 + qrow;
            int xorv = cf * 8;
            uint32_t b0 = *(const uint32_t*)&Bs[n * 72 + ((k0 + qk2) ^ xorv)];
            uint32_t b1 = *(const uint32_t*)&Bs[n * 72 + ((k0 + qk2 + 8) ^ xorv)];
            asm volatile(
                "mma.sync.aligned.m16n8k16.row.col.f32.f16.f16.f32 "
                "{%0,%1,%2,%3}, {%4,%5,%6,%7}, {%8,%9}, {%0,%1,%2,%3};"
                : "+f"(acc[cf][0]), "+f"(acc[cf][1]), "+f"(acc[cf][2]), "+f"(acc[cf][3])
                : "r"(a0), "r"(a1), "r"(a2), "r"(a3), "r"(b0), "r"(b1));
        }
    }

    // epilogue: bias + relu -> fp16 khid
    int row0 = r0 + wr + qrow;
    #pragma unroll
    for (int cf = 0; cf < 8; cf++) {
        int col = cf * 8 + (lane & 3) * 2;
        float bb0 = sb2[col], bb1 = sb2[col + 1];
        __half2 p0 = __floats2half2_rn(fmaxf(acc[cf][0] + bb0, 0.f),
                                       fmaxf(acc[cf][1] + bb1, 0.f));
        __half2 p1 = __floats2half2_rn(fmaxf(acc[cf][2] + bb0, 0.f),
                                       fmaxf(acc[cf][3] + bb1, 0.f));
        *(__half2*)&g_khid[(size_t)row0 * 64 + col]       = p0;
        *(__half2*)&g_khid[(size_t)(row0 + 8) * 64 + col] = p1;
    }
}

// ---------------- W = khid @ w3 + b3 via HMMA, DIRECT register stores ---------
// 128x128 tile, 8 warps (2 row x 4 col). Each warp tile spans exactly one i
// (32 gemm cols). Thread's 8 values per row-half are contiguous in the new
// W layout -> one 16B store each. No epilogue smem staging.
__global__ void __launch_bounds__(256) w3gemm_kernel(
    const float* __restrict__ b3a, const float* __restrict__ b3b)
{
    __shared__ __half As[128 * 72];   // [row][k], stride 72 halves
    __shared__ __half Bs[128 * 72];   // [n][k^swz], stride 72 halves
    __shared__ float sbias[128];

    int rb = blockIdx.x, cb = blockIdx.y;
    size_t r0 = (size_t)rb * 128;
    int set = (r0 >= (size_t)E_PAD) ? 1 : 0;
    const float* b3 = set ? b3b : b3a;
    int t = threadIdx.x;

    if (t < 128) sbias[t] = b3[cb * 128 + t];

    const __half* Ag = g_khid + r0 * 64;
    #pragma unroll
    for (int i = 0; i < 4; i++) {
        int idx = t + 256 * i;
        int r = idx >> 3, c8 = idx & 7;
        *(uint4*)&As[r * 72 + c8 * 8] = *(const uint4*)&Ag[r * 64 + c8 * 8];
    }
    const __half* Bg = g_w3h[set] + cb * 128;
    #pragma unroll
    for (int i = 0; i < 4; i++) {
        int idx = t + 256 * i;
        int k = idx >> 4, n8 = idx & 15;
        uint4 v = *(const uint4*)&Bg[(size_t)k * 1024 + n8 * 8];
        const __half* hv = (const __half*)&v;
        int ksw = k ^ ((n8 & 7) * 8);
        #pragma unroll
        for (int j = 0; j < 8; j++)
            Bs[(n8 * 8 + j) * 72 + ksw] = hv[j];
    }
    __syncthreads();

    int w = t >> 5, lane = t & 31;
    int wr = (w & 1) * 64;
    int wc = (w >> 1) * 32;
    int qrow = lane >> 2;
    int q4   = lane & 3;
    int qk2  = q4 * 2;

    float acc[4][4][4];
    #pragma unroll
    for (int rf = 0; rf < 4; rf++)
        #pragma unroll
        for (int cf = 0; cf < 4; cf++)
            #pragma unroll
            for (int v = 0; v < 4; v++) acc[rf][cf][v] = 0.f;

    #pragma unroll
    for (int ks = 0; ks < 4; ks++) {
        int k0 = ks * 16;
        uint32_t a[4][4], b[4][2];
        #pragma unroll
        for (int rf = 0; rf < 4; rf++) {
            const __half* ap = &As[(wr + rf * 16 + qrow) * 72 + k0 + qk2];
            a[rf][0] = *(const uint32_t*)ap;
            a[rf][1] = *(const uint32_t*)(ap + 8 * 72);
            a[rf][2] = *(const uint32_t*)(ap + 8);
            a[rf][3] = *(const uint32_t*)(ap + 8 * 72 + 8);
        }
        #pragma unroll
        for (int cf = 0; cf < 4; cf++) {
            int n = wc + cf * 8 + qrow;
            int xorv = ((n >> 3) & 7) * 8;
            b[cf][0] = *(const uint32_t*)&Bs[n * 72 + ((k0 + qk2) ^ xorv)];
            b[cf][1] = *(const uint32_t*)&Bs[n * 72 + ((k0 + qk2 + 8) ^ xorv)];
        }
        #pragma unroll
        for (int rf = 0; rf < 4; rf++)
            #pragma unroll
            for (int cf = 0; cf < 4; cf++)
                asm volatile(
                    "mma.sync.aligned.m16n8k16.row.col.f32.f16.f16.f32 "
                    "{%0,%1,%2,%3}, {%4,%5,%6,%7}, {%8,%9}, {%0,%1,%2,%3};"
                    : "+f"(acc[rf][cf][0]), "+f"(acc[rf][cf][1]),
                      "+f"(acc[rf][cf][2]), "+f"(acc[rf][cf][3])
                    : "r"(a[rf][0]), "r"(a[rf][1]), "r"(a[rf][2]), "r"(a[rf][3]),
                      "r"(b[cf][0]), "r"(b[cf][1]));
    }

    // direct epilogue: gemm col n = cb*128 + wc + cf*8 + q4*2 + b.
    // i = cb*4 + (wc>>5) fixed per warp; o = cf*8 + q4*2 + b.
    // position p = i*32 + q4*8 + cf*2 + b  -> thread's 8 values contiguous.
    int i_idx = cb * 4 + (wc >> 5);
    size_t colbase = (size_t)i_idx * 32 + q4 * 8;
    #pragma unroll
    for (int rf = 0; rf < 4; rf++) {
        int row = wr + rf * 16 + qrow;
        uint4 lo, hi;
        uint32_t* lop = (uint32_t*)&lo;
        uint32_t* hip = (uint32_t*)&hi;
        #pragma unroll
        for (int cf = 0; cf < 4; cf++) {
            int n32 = wc + cf * 8 + q4 * 2;
            float bb0 = sbias[n32], bb1 = sbias[n32 + 1];
            __half2 pl = __floats2half2_rn(acc[rf][cf][0] + bb0, acc[rf][cf][1] + bb1);
            __half2 ph = __floats2half2_rn(acc[rf][cf][2] + bb0, acc[rf][cf][3] + bb1);
            lop[cf] = *(uint32_t*)&pl;
            hip[cf] = *(uint32_t*)&ph;
        }
        *(uint4*)&g_Wh[(r0 + row) * 1024 + colbase]     = lo;
        *(uint4*)&g_Wh[(r0 + row + 8) * 1024 + colbase] = hi;
    }
}

// ---------------- per-edge message for the new W layout ----------------
// lane l: q4 = l&3, m = l>>2. Step s loads 16B block (i = m+8s, q4):
// 8 halves = channels o(cf,b) = cf*8 + q4*2 + b. Warp reads 512B contiguous
// per step. Reduce over m via 3 shfl_xor; lane writes channel
// o = (m>>1)*8 + q4*2 + (m&1) with value acc[m].
__global__ void __launch_bounds__(256) edge_msg_kernel(const int* __restrict__ ei,
                                                       const int* __restrict__ eib)
{
    int e = (blockIdx.x * blockDim.x + threadIdx.x) >> 5;
    int lane = threadIdx.x & 31;
    if (e >= E_TOT) return;

    int src, dst; size_t wrow; float cnt;
    if (e < E_MAIN) {
        src = ei[e]; dst = ei[E_MAIN + e];
        wrow = (size_t)e;
        cnt = g_cnt1[dst];
    } else {
        int eb = e - E_MAIN;
        src = eib[eb]; dst = eib[E_BND + eb];
        wrow = (size_t)E_PAD + eb;
        cnt = g_cnt2[dst];
    }
    float scale = 1.0f / fmaxf(cnt, 1.0f);

    float hv = g_h[src * WIDTH + lane];
    const __half* __restrict__ Wp = g_Wh + wrow * 1024;
    int q4 = lane & 3, m = lane >> 2;

    float acc[8];
    #pragma unroll
    for (int k = 0; k < 8; k++) acc[k] = 0.f;

    #pragma unroll
    for (int s = 0; s < 4; s++) {
        int i = m + 8 * s;
        uint4 v = *(const uint4*)(Wp + (size_t)i * 32 + q4 * 8);
        float hi = __shfl_sync(0xffffffffu, hv, i);
        float2 f0 = __half22float2(*reinterpret_cast<const __half2*>(&v.x));
        float2 f1 = __half22float2(*reinterpret_cast<const __half2*>(&v.y));
        float2 f2 = __half22float2(*reinterpret_cast<const __half2*>(&v.z));
        float2 f3 = __half22float2(*reinterpret_cast<const __half2*>(&v.w));
        acc[0] = fmaf(f0.x, hi, acc[0]); acc[1] = fmaf(f0.y, hi, acc[1]);
        acc[2] = fmaf(f1.x, hi, acc[2]); acc[3] = fmaf(f1.y, hi, acc[3]);
        acc[4] = fmaf(f2.x, hi, acc[4]); acc[5] = fmaf(f2.y, hi, acc[5]);
        acc[6] = fmaf(f3.x, hi, acc[6]); acc[7] = fmaf(f3.y, hi, acc[7]);
    }
    #pragma unroll
    for (int k = 0; k < 8; k++) {
        acc[k] += __shfl_xor_sync(0xffffffffu, acc[k], 4);
        acc[k] += __shfl_xor_sync(0xffffffffu, acc[k], 8);
        acc[k] += __shfl_xor_sync(0xffffffffu, acc[k], 16);
    }
    // select acc[m] without dynamic register indexing
    float out = acc[0];
    if (m == 1) out = acc[1];
    else if (m == 2) out = acc[2];
    else if (m == 3) out = acc[3];
    else if (m == 4) out = acc[4];
    else if (m == 5) out = acc[5];
    else if (m == 6) out = acc[6];
    else if (m == 7) out = acc[7];
    int o = (m >> 1) * 8 + q4 * 2 + (m & 1);
    atomicAdd(&g_agg[dst * WIDTH + o], out * scale);
}

// ---------------- node update (consumes + re-zeroes agg; optionally fc2) ------
__global__ void __launch_bounds__(256) node_update_kernel(int last,
                                                          const float* __restrict__ fc2w,
                                                          const float* __restrict__ fc2b,
                                                          float* __restrict__ out) {
    int n = (blockIdx.x * blockDim.x + threadIdx.x) >> 5;
    int lane = threadIdx.x & 31;
    if (n >= N_NODES) return;

    float hv  = g_h[n * WIDTH + lane];
    float acc = g_agg[n * WIDTH + lane] + g_biassum[lane];
    g_agg[n * WIDTH + lane] = 0.f;
    #pragma unroll
    for (int i = 0; i < 32; i++) {
        float hi = __shfl_sync(0xffffffffu, hv, i);
        acc = fmaf(hi, g_rootsum[i * 32 + lane], acc);
    }
    float hnew = fmaxf(acc, 0.f) + g_h0[n * WIDTH + lane];
    g_h[n * WIDTH + lane] = hnew;

    if (last) {
        float v = hnew * fc2w[lane];
        #pragma unroll
        for (int off = 16; off > 0; off >>= 1)
            v += __shfl_xor_sync(0xffffffffu, v, off);
        if (lane == 0) out[n] = v + fc2b[0];
    }
}

// ---------------- host orchestration ----------------
extern "C" void kernel_launch(void* const* d_in, const int* in_sizes, int n_in,
                              void* d_out, int out_size) {
    const float* x    = (const float*)d_in[0];
    const int*   ei   = (const int*)  d_in[1];
    const float* ea   = (const float*)d_in[2];
    const int*   eib  = (const int*)  d_in[3];
    const float* eab  = (const float*)d_in[4];
    const float* fc1w = (const float*)d_in[5];
    const float* fc1b = (const float*)d_in[6];
    const float* fc2w = (const float*)d_in[7];
    const float* fc2b = (const float*)d_in[8];
    const float* k1w1 = (const float*)d_in[9];
    const float* k1b1 = (const float*)d_in[10];
    const float* k1w2 = (const float*)d_in[11];
    const float* k1b2 = (const float*)d_in[12];
    const float* k1w3 = (const float*)d_in[13];
    const float* k1b3 = (const float*)d_in[14];
    const float* root1= (const float*)d_in[15];
    const float* bias1= (const float*)d_in[16];
    const float* k2w1 = (const float*)d_in[17];
    const float* k2b1 = (const float*)d_in[18];
    const float* k2w2 = (const float*)d_in[19];
    const float* k2b2 = (const float*)d_in[20];
    const float* k2w3 = (const float*)d_in[21];
    const float* k2b3 = (const float*)d_in[22];
    const float* root2= (const float*)d_in[23];
    const float* bias2= (const float*)d_in[24];
    float* out = (float*)d_out;

    // ncu profiles launch #4 -> w3gemm_kernel (verify the fix)
    setupB_kernel<<<(KW * 1024 + 255) / 256, 256>>>(root1, bias1, root2, bias2,
                                                    k1w2, k2w2, k1w3, k2w3);   // 1
    setupA_kernel<<<(N_NODES * WIDTH + 255) / 256, 256>>>(x, fc1w, fc1b);      // 2
    kermlp_kernel<<<ROWS_TOT / 128, 256>>>(ea, eab,
                                           k1w1, k1b1, k1b2,
                                           k2w1, k2b1, k2b2);                  // 3
    dim3 ggrid(ROWS_TOT / 128, 1024 / 128);
    w3gemm_kernel<<<ggrid, 256>>>(k1b3, k2b3);                                 // 4
    count_kernel<<<(E_TOT + 255) / 256, 256>>>(ei, eib);                       // 5

    for (int d = 0; d < DEPTH; d++) {
        edge_msg_kernel<<<(E_TOT * 32 + 255) / 256, 256>>>(ei, eib);
        node_update_kernel<<<(N_NODES * 32 + 255) / 256, 256>>>(
            d == DEPTH - 1 ? 1 : 0, fc2w, fc2b, out);
    }
}

// round 13
// speedup vs baseline: 2.9567x; 1.0125x over previous
#include <cuda_runtime.h>
#include <cuda_fp16.h>
#include <stdint.h>

// ---------------- problem constants (fixed by dataset) ----------------
#define N_NODES 20000
#define E_MAIN  100000
#define E_BND   20000
#define E_TOT   (E_MAIN + E_BND)
#define E_PAD   100096            // E_MAIN rounded up to 128
#define EB_PAD  20096             // E_BND  rounded up to 128
#define ROWS_TOT (E_PAD + EB_PAD) // 120192, multiple of 128
#define WIDTH   32
#define KW      64
#define DEPTH   4

// W row layout (1024 halves): element (i,o) at
//   p(i,o) = i*32 + ((o>>1)&3)*8 + (o>>3)*2 + (o&1)

// ---------------- device scratch (no allocations allowed) ----------------
__device__ float g_h0[N_NODES * WIDTH];
__device__ float g_h [N_NODES * WIDTH];
__device__ float g_agg1[N_NODES * WIDTH];   // unscaled sum, main edges
__device__ float g_agg2[N_NODES * WIDTH];   // unscaled sum, boundary edges
__device__ float g_cnt1[N_NODES];
__device__ float g_cnt2[N_NODES];
__device__ __align__(16) __half g_khid[(size_t)ROWS_TOT * KW];   // 15.4 MB
__device__ __align__(16) __half g_w2t[2][KW * KW];               // w2 transposed [n][k]
__device__ __align__(16) __half g_w3t[2][1024 * KW];             // w3 transposed [n][k]
__device__ __align__(16) __half g_Wh[(size_t)ROWS_TOT * 1024];   // 246 MB per-edge weights
__device__ float g_rootsum[WIDTH * WIDTH];
__device__ float g_biassum[WIDTH];

// ---------------- fused setup: fc1 + zeros + transposes + rootsum -------------
__global__ void setup_kernel(const float* __restrict__ x,
                             const float* __restrict__ fc1w,
                             const float* __restrict__ fc1b,
                             const float* __restrict__ r1, const float* __restrict__ b1,
                             const float* __restrict__ r2, const float* __restrict__ b2,
                             const float* __restrict__ w2a, const float* __restrict__ w2b,
                             const float* __restrict__ w3a, const float* __restrict__ w3b) {
    int i = blockIdx.x * blockDim.x + threadIdx.x;
    if (i < N_NODES * WIDTH) {
        int n = i >> 5, c = i & 31;
        float v = fmaf(x[n], fc1w[c], fc1b[c]);
        g_h0[i] = v;
        g_h[i]  = v;
        g_agg1[i] = 0.f;
        g_agg2[i] = 0.f;
    }
    if (i < KW * 1024) {                     // w3 transpose: [k][n] -> [n][k]
        int k = i >> 10, n = i & 1023;
        g_w3t[0][n * KW + k] = __float2half_rn(w3a[i]);
        g_w3t[1][n * KW + k] = __float2half_rn(w3b[i]);
    }
    if (i < KW * KW) {                       // w2 transpose
        int k = i >> 6, n = i & 63;
        g_w2t[0][n * KW + k] = __float2half_rn(w2a[i]);
        g_w2t[1][n * KW + k] = __float2half_rn(w2b[i]);
    }
    if (i < N_NODES) { g_cnt1[i] = 0.f; g_cnt2[i] = 0.f; }
    if (i < WIDTH * WIDTH) g_rootsum[i] = r1[i] + r2[i];
    if (i < WIDTH)         g_biassum[i] = b1[i] + b2[i];
}

__global__ void count_kernel(const int* __restrict__ ei,
                             const int* __restrict__ eib) {
    int e = blockIdx.x * blockDim.x + threadIdx.x;
    if (e < E_MAIN) {
        atomicAdd(&g_cnt1[ei[E_MAIN + e]], 1.0f);
    } else if (e < E_TOT) {
        int eb = e - E_MAIN;
        atomicAdd(&g_cnt2[eib[E_BND + eb]], 1.0f);
    }
}

// ---------------- kernel MLP via HMMA (vectorized B fill from g_w2t) ----------
__global__ void __launch_bounds__(256) kermlp_kernel(
    const float* __restrict__ ea1, const float* __restrict__ ea2,
    const float* __restrict__ k1w1, const float* __restrict__ k1b1, const float* __restrict__ k1b2,
    const float* __restrict__ k2w1, const float* __restrict__ k2b1, const float* __restrict__ k2b2)
{
    __shared__ float sea[128 * 6];
    __shared__ float sw1[6 * 64];
    __shared__ float sb1[64];
    __shared__ float sb2[64];
    __shared__ __half As[128 * 72];   // [edge][h1-k], stride 72
    __shared__ __half Bs[64 * 72];    // [n][k ^ swz], stride 72

    int t = threadIdx.x;
    int r0 = blockIdx.x * 128;
    int set = (r0 >= E_PAD) ? 1 : 0;
    int ebase = set ? (r0 - E_PAD) : r0;
    int valid = set ? E_BND : E_MAIN;
    const float* ea = set ? ea2 : ea1;
    const float* w1 = set ? k2w1 : k1w1;
    const float* b1 = set ? k2b1 : k1b1;
    const float* b2 = set ? k2b2 : k1b2;

    for (int i = t; i < 6 * 64; i += 256) sw1[i] = w1[i];
    if (t < 64) { sb1[t] = b1[t]; sb2[t] = b2[t]; }
    #pragma unroll
    for (int i = 0; i < 3; i++) {
        int idx = t + 256 * i;                 // 0..767
        int e = idx / 6, c = idx - e * 6;
        int eg = ebase + e;
        sea[idx] = (eg < valid) ? ea[(size_t)eg * 6 + c] : 0.f;
    }
    // B tile from pre-transposed w2t: vector loads + swizzled vector stores
    {
        int idx = t;                           // 0..255: but need 64*8=512 items
        #pragma unroll
        for (int i = 0; i < 2; i++) {
            int id = idx + 256 * i;            // 0..511
            int n = id >> 3, c8 = id & 7;
            uint4 v = *(const uint4*)&g_w2t[set][n * KW + c8 * 8];
            int ksw = (c8 * 8) ^ ((n >> 3) * 8);
            *(uint4*)&Bs[n * 72 + ksw] = v;
        }
    }
    __syncthreads();

    // layer1: thread t -> edge t>>1, outputs (t&1)*32..+31
    {
        int e = t >> 1, ob = (t & 1) * 32;
        float a0 = sea[e * 6 + 0], a1 = sea[e * 6 + 1], a2 = sea[e * 6 + 2];
        float a3 = sea[e * 6 + 3], a4 = sea[e * 6 + 4], a5 = sea[e * 6 + 5];
        #pragma unroll
        for (int o = 0; o < 32; o += 2) {
            int oc = ob + o;
            float v0 = sb1[oc], v1 = sb1[oc + 1];
            v0 = fmaf(a0, sw1[0 * 64 + oc], v0); v1 = fmaf(a0, sw1[0 * 64 + oc + 1], v1);
            v0 = fmaf(a1, sw1[1 * 64 + oc], v0); v1 = fmaf(a1, sw1[1 * 64 + oc + 1], v1);
            v0 = fmaf(a2, sw1[2 * 64 + oc], v0); v1 = fmaf(a2, sw1[2 * 64 + oc + 1], v1);
            v0 = fmaf(a3, sw1[3 * 64 + oc], v0); v1 = fmaf(a3, sw1[3 * 64 + oc + 1], v1);
            v0 = fmaf(a4, sw1[4 * 64 + oc], v0); v1 = fmaf(a4, sw1[4 * 64 + oc + 1], v1);
            v0 = fmaf(a5, sw1[5 * 64 + oc], v0); v1 = fmaf(a5, sw1[5 * 64 + oc + 1], v1);
            __half2 p = __floats2half2_rn(fmaxf(v0, 0.f), fmaxf(v1, 0.f));
            *(__half2*)&As[e * 72 + oc] = p;
        }
    }
    __syncthreads();

    int w = t >> 5, lane = t & 31;
    int wr = w * 16;
    int qrow = lane >> 2;
    int qk2  = (lane & 3) * 2;

    float acc[8][4];
    #pragma unroll
    for (int cf = 0; cf < 8; cf++)
        #pragma unroll
        for (int v = 0; v < 4; v++) acc[cf][v] = 0.f;

    #pragma unroll
    for (int ks = 0; ks < 4; ks++) {
        int k0 = ks * 16;
        const __half* ap = &As[(wr + qrow) * 72 + k0 + qk2];
        uint32_t a0 = *(const uint32_t*)ap;
        uint32_t a1 = *(const uint32_t*)(ap + 8 * 72);
        uint32_t a2 = *(const uint32_t*)(ap + 8);
        uint32_t a3 = *(const uint32_t*)(ap + 8 * 72 + 8);
        #pragma unroll
        for (int cf = 0; cf < 8; cf++) {
            int n = cf * 8 + qrow;
            int xorv = cf * 8;
            uint32_t b0 = *(const uint32_t*)&Bs[n * 72 + ((k0 + qk2) ^ xorv)];
            uint32_t b1 = *(const uint32_t*)&Bs[n * 72 + ((k0 + qk2 + 8) ^ xorv)];
            asm volatile(
                "mma.sync.aligned.m16n8k16.row.col.f32.f16.f16.f32 "
                "{%0,%1,%2,%3}, {%4,%5,%6,%7}, {%8,%9}, {%0,%1,%2,%3};"
                : "+f"(acc[cf][0]), "+f"(acc[cf][1]), "+f"(acc[cf][2]), "+f"(acc[cf][3])
                : "r"(a0), "r"(a1), "r"(a2), "r"(a3), "r"(b0), "r"(b1));
        }
    }

    int row0 = r0 + wr + qrow;
    #pragma unroll
    for (int cf = 0; cf < 8; cf++) {
        int col = cf * 8 + (lane & 3) * 2;
        float bb0 = sb2[col], bb1 = sb2[col + 1];
        __half2 p0 = __floats2half2_rn(fmaxf(acc[cf][0] + bb0, 0.f),
                                       fmaxf(acc[cf][1] + bb1, 0.f));
        __half2 p1 = __floats2half2_rn(fmaxf(acc[cf][2] + bb0, 0.f),
                                       fmaxf(acc[cf][3] + bb1, 0.f));
        *(__half2*)&g_khid[(size_t)row0 * 64 + col]       = p0;
        *(__half2*)&g_khid[(size_t)(row0 + 8) * 64 + col] = p1;
    }
}

// ---------------- W = khid @ w3 + b3 via HMMA, direct stores ------------------
__global__ void __launch_bounds__(256) w3gemm_kernel(
    const float* __restrict__ b3a, const float* __restrict__ b3b)
{
    __shared__ __half As[128 * 72];   // [row][k], stride 72
    __shared__ __half Bs[128 * 72];   // [n][k^swz], stride 72
    __shared__ float sbias[128];

    int rb = blockIdx.x, cb = blockIdx.y;
    size_t r0 = (size_t)rb * 128;
    int set = (r0 >= (size_t)E_PAD) ? 1 : 0;
    const float* b3 = set ? b3b : b3a;
    int t = threadIdx.x;

    if (t < 128) sbias[t] = b3[cb * 128 + t];

    const __half* Ag = g_khid + r0 * 64;
    #pragma unroll
    for (int i = 0; i < 4; i++) {
        int idx = t + 256 * i;
        int r = idx >> 3, c8 = idx & 7;
        *(uint4*)&As[r * 72 + c8 * 8] = *(const uint4*)&Ag[r * 64 + c8 * 8];
    }
    // B tile from pre-transposed w3t: vector loads + swizzled vector stores
    const __half* Bg = g_w3t[set] + (size_t)cb * 128 * KW;
    #pragma unroll
    for (int i = 0; i < 4; i++) {
        int idx = t + 256 * i;                 // 0..1023
        int n = idx >> 3, c8 = idx & 7;
        uint4 v = *(const uint4*)&Bg[n * KW + c8 * 8];
        int ksw = (c8 * 8) ^ (((n >> 3) & 7) * 8);
        *(uint4*)&Bs[n * 72 + ksw] = v;
    }
    __syncthreads();

    int w = t >> 5, lane = t & 31;
    int wr = (w & 1) * 64;
    int wc = (w >> 1) * 32;
    int qrow = lane >> 2;
    int q4   = lane & 3;
    int qk2  = q4 * 2;

    float acc[4][4][4];
    #pragma unroll
    for (int rf = 0; rf < 4; rf++)
        #pragma unroll
        for (int cf = 0; cf < 4; cf++)
            #pragma unroll
            for (int v = 0; v < 4; v++) acc[rf][cf][v] = 0.f;

    #pragma unroll
    for (int ks = 0; ks < 4; ks++) {
        int k0 = ks * 16;
        uint32_t a[4][4], b[4][2];
        #pragma unroll
        for (int rf = 0; rf < 4; rf++) {
            const __half* ap = &As[(wr + rf * 16 + qrow) * 72 + k0 + qk2];
            a[rf][0] = *(const uint32_t*)ap;
            a[rf][1] = *(const uint32_t*)(ap + 8 * 72);
            a[rf][2] = *(const uint32_t*)(ap + 8);
            a[rf][3] = *(const uint32_t*)(ap + 8 * 72 + 8);
        }
        #pragma unroll
        for (int cf = 0; cf < 4; cf++) {
            int n = wc + cf * 8 + qrow;
            int xorv = ((n >> 3) & 7) * 8;
            b[cf][0] = *(const uint32_t*)&Bs[n * 72 + ((k0 + qk2) ^ xorv)];
            b[cf][1] = *(const uint32_t*)&Bs[n * 72 + ((k0 + qk2 + 8) ^ xorv)];
        }
        #pragma unroll
        for (int rf = 0; rf < 4; rf++)
            #pragma unroll
            for (int cf = 0; cf < 4; cf++)
                asm volatile(
                    "mma.sync.aligned.m16n8k16.row.col.f32.f16.f16.f32 "
                    "{%0,%1,%2,%3}, {%4,%5,%6,%7}, {%8,%9}, {%0,%1,%2,%3};"
                    : "+f"(acc[rf][cf][0]), "+f"(acc[rf][cf][1]),
                      "+f"(acc[rf][cf][2]), "+f"(acc[rf][cf][3])
                    : "r"(a[rf][0]), "r"(a[rf][1]), "r"(a[rf][2]), "r"(a[rf][3]),
                      "r"(b[cf][0]), "r"(b[cf][1]));
    }

    int i_idx = cb * 4 + (wc >> 5);
    size_t colbase = (size_t)i_idx * 32 + q4 * 8;
    #pragma unroll
    for (int rf = 0; rf < 4; rf++) {
        int row = wr + rf * 16 + qrow;
        uint4 lo, hi;
        uint32_t* lop = (uint32_t*)&lo;
        uint32_t* hip = (uint32_t*)&hi;
        #pragma unroll
        for (int cf = 0; cf < 4; cf++) {
            int n32 = wc + cf * 8 + q4 * 2;
            float bb0 = sbias[n32], bb1 = sbias[n32 + 1];
            __half2 pl = __floats2half2_rn(acc[rf][cf][0] + bb0, acc[rf][cf][1] + bb1);
            __half2 ph = __floats2half2_rn(acc[rf][cf][2] + bb0, acc[rf][cf][3] + bb1);
            lop[cf] = *(uint32_t*)&pl;
            hip[cf] = *(uint32_t*)&ph;
        }
        *(uint4*)&g_Wh[(r0 + row) * 1024 + colbase]     = lo;
        *(uint4*)&g_Wh[(r0 + row + 8) * 1024 + colbase] = hi;
    }
}

// ---------------- per-edge message (unscaled; scaling in node_update) ---------
__global__ void __launch_bounds__(256) edge_msg_kernel(const int* __restrict__ ei,
                                                       const int* __restrict__ eib)
{
    int e = (blockIdx.x * blockDim.x + threadIdx.x) >> 5;
    int lane = threadIdx.x & 31;
    if (e >= E_TOT) return;

    int src, dst; size_t wrow; float* aggp;
    if (e < E_MAIN) {
        src = ei[e]; dst = ei[E_MAIN + e];
        wrow = (size_t)e;
        aggp = g_agg1;
    } else {
        int eb = e - E_MAIN;
        src = eib[eb]; dst = eib[E_BND + eb];
        wrow = (size_t)E_PAD + eb;
        aggp = g_agg2;
    }

    float hv = g_h[src * WIDTH + lane];
    const __half* __restrict__ Wp = g_Wh + wrow * 1024;
    int q4 = lane & 3, m = lane >> 2;

    float acc[8];
    #pragma unroll
    for (int k = 0; k < 8; k++) acc[k] = 0.f;

    #pragma unroll
    for (int s = 0; s < 4; s++) {
        int i = m + 8 * s;
        uint4 v = *(const uint4*)(Wp + (size_t)i * 32 + q4 * 8);
        float hi = __shfl_sync(0xffffffffu, hv, i);
        float2 f0 = __half22float2(*reinterpret_cast<const __half2*>(&v.x));
        float2 f1 = __half22float2(*reinterpret_cast<const __half2*>(&v.y));
        float2 f2 = __half22float2(*reinterpret_cast<const __half2*>(&v.z));
        float2 f3 = __half22float2(*reinterpret_cast<const __half2*>(&v.w));
        acc[0] = fmaf(f0.x, hi, acc[0]); acc[1] = fmaf(f0.y, hi, acc[1]);
        acc[2] = fmaf(f1.x, hi, acc[2]); acc[3] = fmaf(f1.y, hi, acc[3]);
        acc[4] = fmaf(f2.x, hi, acc[4]); acc[5] = fmaf(f2.y, hi, acc[5]);
        acc[6] = fmaf(f3.x, hi, acc[6]); acc[7] = fmaf(f3.y, hi, acc[7]);
    }
    #pragma unroll
    for (int k = 0; k < 8; k++) {
        acc[k] += __shfl_xor_sync(0xffffffffu, acc[k], 4);
        acc[k] += __shfl_xor_sync(0xffffffffu, acc[k], 8);
        acc[k] += __shfl_xor_sync(0xffffffffu, acc[k], 16);
    }
    float out = acc[0];
    if (m == 1) out = acc[1];
    else if (m == 2) out = acc[2];
    else if (m == 3) out = acc[3];
    else if (m == 4) out = acc[4];
    else if (m == 5) out = acc[5];
    else if (m == 6) out = acc[6];
    else if (m == 7) out = acc[7];
    int o = (m >> 1) * 8 + q4 * 2 + (m & 1);
    atomicAdd(&aggp[dst * WIDTH + o], out);
}

// ---------------- node update: scale both agg sets, root, relu, +h0 -----------
__global__ void __launch_bounds__(256) node_update_kernel(int last,
                                                          const float* __restrict__ fc2w,
                                                          const float* __restrict__ fc2b,
                                                          float* __restrict__ out) {
    int n = (blockIdx.x * blockDim.x + threadIdx.x) >> 5;
    int lane = threadIdx.x & 31;
    if (n >= N_NODES) return;

    float s1 = 1.0f / fmaxf(g_cnt1[n], 1.0f);
    float s2 = 1.0f / fmaxf(g_cnt2[n], 1.0f);
    int idx = n * WIDTH + lane;
    float hv  = g_h[idx];
    float acc = g_agg1[idx] * s1 + g_agg2[idx] * s2 + g_biassum[lane];
    g_agg1[idx] = 0.f;
    g_agg2[idx] = 0.f;
    #pragma unroll
    for (int i = 0; i < 32; i++) {
        float hi = __shfl_sync(0xffffffffu, hv, i);
        acc = fmaf(hi, g_rootsum[i * 32 + lane], acc);
    }
    float hnew = fmaxf(acc, 0.f) + g_h0[idx];
    g_h[idx] = hnew;

    if (last) {
        float v = hnew * fc2w[lane];
        #pragma unroll
        for (int off = 16; off > 0; off >>= 1)
            v += __shfl_xor_sync(0xffffffffu, v, off);
        if (lane == 0) out[n] = v + fc2b[0];
    }
}

// ---------------- host orchestration ----------------
extern "C" void kernel_launch(void* const* d_in, const int* in_sizes, int n_in,
                              void* d_out, int out_size) {
    const float* x    = (const float*)d_in[0];
    const int*   ei   = (const int*)  d_in[1];
    const float* ea   = (const float*)d_in[2];
    const int*   eib  = (const int*)  d_in[3];
    const float* eab  = (const float*)d_in[4];
    const float* fc1w = (const float*)d_in[5];
    const float* fc1b = (const float*)d_in[6];
    const float* fc2w = (const float*)d_in[7];
    const float* fc2b = (const float*)d_in[8];
    const float* k1w1 = (const float*)d_in[9];
    const float* k1b1 = (const float*)d_in[10];
    const float* k1w2 = (const float*)d_in[11];
    const float* k1b2 = (const float*)d_in[12];
    const float* k1w3 = (const float*)d_in[13];
    const float* k1b3 = (const float*)d_in[14];
    const float* root1= (const float*)d_in[15];
    const float* bias1= (const float*)d_in[16];
    const float* k2w1 = (const float*)d_in[17];
    const float* k2b1 = (const float*)d_in[18];
    const float* k2w2 = (const float*)d_in[19];
    const float* k2b2 = (const float*)d_in[20];
    const float* k2w3 = (const float*)d_in[21];
    const float* k2b3 = (const float*)d_in[22];
    const float* root2= (const float*)d_in[23];
    const float* bias2= (const float*)d_in[24];
    float* out = (float*)d_out;

    // ncu profiles launch #4 -> first edge_msg_kernel this round
    setup_kernel<<<(N_NODES * WIDTH + 255) / 256, 256>>>(
        x, fc1w, fc1b, root1, bias1, root2, bias2,
        k1w2, k2w2, k1w3, k2w3);                                               // 1
    kermlp_kernel<<<ROWS_TOT / 128, 256>>>(ea, eab,
                                           k1w1, k1b1, k1b2,
                                           k2w1, k2b1, k2b2);                  // 2
    dim3 ggrid(ROWS_TOT / 128, 1024 / 128);
    w3gemm_kernel<<<ggrid, 256>>>(k1b3, k2b3);                                 // 3

    for (int d = 0; d < DEPTH; d++) {
        edge_msg_kernel<<<(E_TOT * 32 + 255) / 256, 256>>>(ei, eib);           // 4 on d=0
        if (d == 0)
            count_kernel<<<(E_TOT + 255) / 256, 256>>>(ei, eib);               // 5 (before first node_update)
        node_update_kernel<<<(N_NODES * 32 + 255) / 256, 256>>>(
            d == DEPTH - 1 ? 1 : 0, fc2w, fc2b, out);
    }
}